// round 1
// baseline (speedup 1.0000x reference)
#include <cuda_runtime.h>

// ---------------------------------------------------------------------------
// MultiHeadAttention: out = (softmax((XWq)(XWk)^T/sqrt(d) + mask)(XWv)) Wo + b
// Shapes: Q/K/V [1024, 8, 512] fp32; heads=8, d_head=64.
// fp32 SIMT baseline using packed fma.rn.f32x2 (2x fp32 FMA throughput).
// ---------------------------------------------------------------------------

#define L_SEQ 1024
#define NB    8
#define NH    8
#define DH    64
#define DM    512
#define M_TOK (L_SEQ * NB)   // 8192 tokens

// Scratch: projections + attention context (allocation-free rule -> device globals)
__device__ float g_q[M_TOK * DM];
__device__ float g_k[M_TOK * DM];
__device__ float g_v[M_TOK * DM];
__device__ float g_ctx[M_TOK * DM];

// ---------------- packed f32x2 helpers ----------------
__device__ __forceinline__ unsigned long long pk2(float lo, float hi) {
    unsigned long long r;
    asm("mov.b64 %0, {%1, %2};" : "=l"(r) : "f"(lo), "f"(hi));
    return r;
}
__device__ __forceinline__ void upk2(unsigned long long v, float& lo, float& hi) {
    asm("mov.b64 {%0, %1}, %2;" : "=f"(lo), "=f"(hi) : "l"(v));
}
__device__ __forceinline__ unsigned long long ffma2(unsigned long long a,
                                                    unsigned long long b,
                                                    unsigned long long c) {
    unsigned long long d;
    asm("fma.rn.f32x2 %0, %1, %2, %3;" : "=l"(d) : "l"(a), "l"(b), "l"(c));
    return d;
}
__device__ __forceinline__ unsigned long long fmul2(unsigned long long a,
                                                    unsigned long long b) {
    unsigned long long d;
    asm("mul.rn.f32x2 %0, %1, %2;" : "=l"(d) : "l"(a), "l"(b));
    return d;
}

// ---------------- GEMM + bias: C[M,N] = A[M,K] @ W[K,N] + bias[N] ----------------
#define BM 128
#define BN 64
#define BK 16

__global__ __launch_bounds__(256) void sgemm_bias(
    const float* __restrict__ A, const float* __restrict__ W,
    const float* __restrict__ bias, float* __restrict__ C,
    int M, int N, int K)
{
    __shared__ float As[BK][BM];   // transposed A tile: As[k][m]
    __shared__ float Bs[BK][BN];   // natural B tile:   Bs[k][n]

    const int tid = threadIdx.x;
    const int tx = tid & 15;        // 16 threads over N
    const int ty = tid >> 4;        // 16 threads over M
    const int m0 = blockIdx.y * BM;
    const int n0 = blockIdx.x * BN;
    const int row = ty * 8;         // 8 rows per thread
    const int col = tx * 4;         // 4 cols per thread (2 packed pairs)

    unsigned long long acc[8][2];
#pragma unroll
    for (int i = 0; i < 8; i++) { acc[i][0] = 0ull; acc[i][1] = 0ull; }

    // load coordinates
    const int ar0 = tid >> 2;            // A float4 id -> row (0..63), +64 for 2nd
    const int ac0 = (tid & 3) * 4;       // A col within BK
    const int br  = tid >> 4;            // B row within BK
    const int bc  = (tid & 15) * 4;      // B col within BN

    for (int k0 = 0; k0 < K; k0 += BK) {
        // A tile 128x16 -> transposed store
#pragma unroll
        for (int i = 0; i < 2; i++) {
            int r = ar0 + i * 64;
            float4 v = *(const float4*)&A[(m0 + r) * K + k0 + ac0];
            As[ac0 + 0][r] = v.x;
            As[ac0 + 1][r] = v.y;
            As[ac0 + 2][r] = v.z;
            As[ac0 + 3][r] = v.w;
        }
        // B tile 16x64 -> natural store
        {
            float4 v = *(const float4*)&W[(k0 + br) * N + n0 + bc];
            *(float4*)&Bs[br][bc] = v;
        }
        __syncthreads();

#pragma unroll
        for (int k = 0; k < BK; k++) {
            float4 a0 = *(float4*)&As[k][row];
            float4 a1 = *(float4*)&As[k][row + 4];
            float4 b  = *(float4*)&Bs[k][col];
            unsigned long long pb0 = pk2(b.x, b.y);
            unsigned long long pb1 = pk2(b.z, b.w);
            float av[8] = {a0.x, a0.y, a0.z, a0.w, a1.x, a1.y, a1.z, a1.w};
#pragma unroll
            for (int i = 0; i < 8; i++) {
                unsigned long long pa = pk2(av[i], av[i]);
                acc[i][0] = ffma2(pa, pb0, acc[i][0]);
                acc[i][1] = ffma2(pa, pb1, acc[i][1]);
            }
        }
        __syncthreads();
    }

    const float b0 = bias[n0 + col + 0];
    const float b1 = bias[n0 + col + 1];
    const float b2 = bias[n0 + col + 2];
    const float b3 = bias[n0 + col + 3];
#pragma unroll
    for (int i = 0; i < 8; i++) {
        float c0, c1, c2, c3;
        upk2(acc[i][0], c0, c1);
        upk2(acc[i][1], c2, c3);
        float4 o = make_float4(c0 + b0, c1 + b1, c2 + b2, c3 + b3);
        *(float4*)&C[(m0 + row + i) * N + n0 + col] = o;
    }
}

// ---------------- flash attention (per (b,h), 64-row Q tile) ----------------
// q,k,v layout: [L, B, DM] with head slice at h*64. Scale folded into Q load.
__global__ __launch_bounds__(256) void flash_attn(
    const float* __restrict__ q, const float* __restrict__ k,
    const float* __restrict__ v, const float* __restrict__ mask,
    float* __restrict__ ctx)
{
    __shared__ float Qst[DH * 64];  // [d][row]   (transposed)
    __shared__ float Kst[DH * 64];  // [d][col]   (transposed); reused as P [row][key]
    __shared__ float Vs[64 * DH];   // [key][d]   (natural)

    const int tid = threadIdx.x;
    const int tx = tid & 15;        // 16 over key/out cols
    const int ty = tid >> 4;        // 16 over q rows
    const int bh = blockIdx.y;
    const int b  = bh >> 3;
    const int h  = bh & 7;
    const int l0 = blockIdx.x * 64;
    const int hoff = h * DH;

    // Q tile load (scaled by 1/sqrt(64)), store transposed
#pragma unroll
    for (int i = 0; i < 4; i++) {
        int id = tid + i * 256;
        int r = id >> 4;
        int c = (id & 15) * 4;
        float4 w = *(const float4*)&q[((l0 + r) * NB + b) * DM + hoff + c];
        Qst[(c + 0) * 64 + r] = w.x * 0.125f;
        Qst[(c + 1) * 64 + r] = w.y * 0.125f;
        Qst[(c + 2) * 64 + r] = w.z * 0.125f;
        Qst[(c + 3) * 64 + r] = w.w * 0.125f;
    }

    unsigned long long O[4][2];
#pragma unroll
    for (int i = 0; i < 4; i++) { O[i][0] = 0ull; O[i][1] = 0ull; }
    float mrun[4], lrun[4];
#pragma unroll
    for (int i = 0; i < 4; i++) { mrun[i] = -1e30f; lrun[i] = 0.0f; }

    for (int t = 0; t < L_SEQ / 64; t++) {
        const int k0 = t * 64;
        // load K (transposed) and V (natural)
#pragma unroll
        for (int i = 0; i < 4; i++) {
            int id = tid + i * 256;
            int r = id >> 4;
            int c = (id & 15) * 4;
            float4 w = *(const float4*)&k[((k0 + r) * NB + b) * DM + hoff + c];
            Kst[(c + 0) * 64 + r] = w.x;
            Kst[(c + 1) * 64 + r] = w.y;
            Kst[(c + 2) * 64 + r] = w.z;
            Kst[(c + 3) * 64 + r] = w.w;
            float4 u = *(const float4*)&v[((k0 + r) * NB + b) * DM + hoff + c];
            *(float4*)&Vs[r * 64 + c] = u;
        }
        __syncthreads();

        // S = Qt @ Kt^T (scaled), packed over key-col pairs
        unsigned long long S[4][2];
#pragma unroll
        for (int i = 0; i < 4; i++) { S[i][0] = 0ull; S[i][1] = 0ull; }
#pragma unroll 8
        for (int d = 0; d < DH; d++) {
            float4 bb = *(float4*)&Kst[d * 64 + tx * 4];
            float4 aa = *(float4*)&Qst[d * 64 + ty * 4];
            unsigned long long pb0 = pk2(bb.x, bb.y);
            unsigned long long pb1 = pk2(bb.z, bb.w);
            float av[4] = {aa.x, aa.y, aa.z, aa.w};
#pragma unroll
            for (int i = 0; i < 4; i++) {
                unsigned long long pa = pk2(av[i], av[i]);
                S[i][0] = ffma2(pa, pb0, S[i][0]);
                S[i][1] = ffma2(pa, pb1, S[i][1]);
            }
        }

        // unpack, add mask, online softmax
        float s[4][4];
#pragma unroll
        for (int i = 0; i < 4; i++) {
            upk2(S[i][0], s[i][0], s[i][1]);
            upk2(S[i][1], s[i][2], s[i][3]);
            float4 mk = *(const float4*)&mask[(l0 + ty * 4 + i) * L_SEQ + k0 + tx * 4];
            s[i][0] += mk.x; s[i][1] += mk.y; s[i][2] += mk.z; s[i][3] += mk.w;
        }
        float p[4][4];
#pragma unroll
        for (int i = 0; i < 4; i++) {
            float mp = fmaxf(fmaxf(s[i][0], s[i][1]), fmaxf(s[i][2], s[i][3]));
#pragma unroll
            for (int o = 8; o >= 1; o >>= 1)
                mp = fmaxf(mp, __shfl_xor_sync(0xffffffffu, mp, o, 16));
            float mnew = fmaxf(mrun[i], mp);
            float alpha = __expf(mrun[i] - mnew);
            mrun[i] = mnew;
            float ls = 0.0f;
#pragma unroll
            for (int j = 0; j < 4; j++) { p[i][j] = __expf(s[i][j] - mnew); ls += p[i][j]; }
#pragma unroll
            for (int o = 8; o >= 1; o >>= 1)
                ls += __shfl_xor_sync(0xffffffffu, ls, o, 16);
            lrun[i] = lrun[i] * alpha + ls;
            unsigned long long pal = pk2(alpha, alpha);
            O[i][0] = fmul2(O[i][0], pal);
            O[i][1] = fmul2(O[i][1], pal);
        }
        __syncthreads();   // everyone finished reading Kst

        // write P into Kst buffer as [row][key]
#pragma unroll
        for (int i = 0; i < 4; i++) {
            float4 w = make_float4(p[i][0], p[i][1], p[i][2], p[i][3]);
            *(float4*)&Kst[(ty * 4 + i) * 64 + tx * 4] = w;
        }
        __syncthreads();

        // O += P @ V, packed over output-dim pairs
#pragma unroll 8
        for (int kk = 0; kk < 64; kk++) {
            float4 bb = *(float4*)&Vs[kk * 64 + tx * 4];
            unsigned long long pb0 = pk2(bb.x, bb.y);
            unsigned long long pb1 = pk2(bb.z, bb.w);
#pragma unroll
            for (int i = 0; i < 4; i++) {
                float a = Kst[(ty * 4 + i) * 64 + kk];
                unsigned long long pa = pk2(a, a);
                O[i][0] = ffma2(pa, pb0, O[i][0]);
                O[i][1] = ffma2(pa, pb1, O[i][1]);
            }
        }
        __syncthreads();   // before next tile overwrites Kst/Vs
    }

    // normalize + write context
#pragma unroll
    for (int i = 0; i < 4; i++) {
        float inv = 1.0f / lrun[i];
        float c0, c1, c2, c3;
        upk2(O[i][0], c0, c1);
        upk2(O[i][1], c2, c3);
        float4 o = make_float4(c0 * inv, c1 * inv, c2 * inv, c3 * inv);
        *(float4*)&ctx[((l0 + ty * 4 + i) * NB + b) * DM + hoff + tx * 4] = o;
    }
}

// ---------------- launch ----------------
extern "C" void kernel_launch(void* const* d_in, const int* in_sizes, int n_in,
                              void* d_out, int out_size) {
    (void)in_sizes; (void)n_in; (void)out_size;
    const float* Q    = (const float*)d_in[0];
    const float* K    = (const float*)d_in[1];
    const float* V    = (const float*)d_in[2];
    const float* mask = (const float*)d_in[3];
    const float* Wq   = (const float*)d_in[4];
    const float* bq   = (const float*)d_in[5];
    const float* Wk   = (const float*)d_in[6];
    const float* bk   = (const float*)d_in[7];
    const float* Wv   = (const float*)d_in[8];
    const float* bv   = (const float*)d_in[9];
    const float* Wo   = (const float*)d_in[10];
    const float* bo   = (const float*)d_in[11];
    float* out = (float*)d_out;

    float *pq, *pk, *pv, *pctx;
    cudaGetSymbolAddress((void**)&pq,   g_q);
    cudaGetSymbolAddress((void**)&pk,   g_k);
    cudaGetSymbolAddress((void**)&pv,   g_v);
    cudaGetSymbolAddress((void**)&pctx, g_ctx);

    dim3 gg(DM / BN, M_TOK / BM);   // (8, 64)
    sgemm_bias<<<gg, 256>>>(Q, Wq, bq, pq, M_TOK, DM, DM);
    sgemm_bias<<<gg, 256>>>(K, Wk, bk, pk, M_TOK, DM, DM);
    sgemm_bias<<<gg, 256>>>(V, Wv, bv, pv, M_TOK, DM, DM);

    dim3 ga(L_SEQ / 64, NB * NH);   // (16, 64)
    flash_attn<<<ga, 256>>>(pq, pk, pv, mask, pctx);

    sgemm_bias<<<gg, 256>>>(pctx, Wo, bo, out, M_TOK, DM, DM);
}

// round 2
// speedup vs baseline: 1.0000x; 1.0000x over previous
#include <cuda_runtime.h>

// ---------------------------------------------------------------------------
// MultiHeadAttention: out = (softmax((XWq)(XWk)^T/sqrt(d) + mask)(XWv)) Wo + b
// Shapes: Q/K/V [1024, 8, 512] fp32; heads=8, d_head=64.
// fp32 SIMT baseline using packed fma.rn.f32x2 (2x fp32 FMA throughput).
// ---------------------------------------------------------------------------

#define L_SEQ 1024
#define NB    8
#define NH    8
#define DH    64
#define DM    512
#define M_TOK (L_SEQ * NB)   // 8192 tokens

// Scratch: projections + attention context (allocation-free rule -> device globals)
__device__ float g_q[M_TOK * DM];
__device__ float g_k[M_TOK * DM];
__device__ float g_v[M_TOK * DM];
__device__ float g_ctx[M_TOK * DM];

// ---------------- packed f32x2 helpers ----------------
__device__ __forceinline__ unsigned long long pk2(float lo, float hi) {
    unsigned long long r;
    asm("mov.b64 %0, {%1, %2};" : "=l"(r) : "f"(lo), "f"(hi));
    return r;
}
__device__ __forceinline__ void upk2(unsigned long long v, float& lo, float& hi) {
    asm("mov.b64 {%0, %1}, %2;" : "=f"(lo), "=f"(hi) : "l"(v));
}
__device__ __forceinline__ unsigned long long ffma2(unsigned long long a,
                                                    unsigned long long b,
                                                    unsigned long long c) {
    unsigned long long d;
    asm("fma.rn.f32x2 %0, %1, %2, %3;" : "=l"(d) : "l"(a), "l"(b), "l"(c));
    return d;
}
__device__ __forceinline__ unsigned long long fmul2(unsigned long long a,
                                                    unsigned long long b) {
    unsigned long long d;
    asm("mul.rn.f32x2 %0, %1, %2;" : "=l"(d) : "l"(a), "l"(b));
    return d;
}

// ---------------- GEMM + bias: C[M,N] = A[M,K] @ W[K,N] + bias[N] ----------------
#define BM 128
#define BN 64
#define BK 16

__global__ __launch_bounds__(256) void sgemm_bias(
    const float* __restrict__ A, const float* __restrict__ W,
    const float* __restrict__ bias, float* __restrict__ C,
    int M, int N, int K)
{
    __shared__ float As[BK][BM];   // transposed A tile: As[k][m]
    __shared__ float Bs[BK][BN];   // natural B tile:   Bs[k][n]

    const int tid = threadIdx.x;
    const int tx = tid & 15;        // 16 threads over N
    const int ty = tid >> 4;        // 16 threads over M
    const int m0 = blockIdx.y * BM;
    const int n0 = blockIdx.x * BN;
    const int row = ty * 8;         // 8 rows per thread
    const int col = tx * 4;         // 4 cols per thread (2 packed pairs)

    unsigned long long acc[8][2];
#pragma unroll
    for (int i = 0; i < 8; i++) { acc[i][0] = 0ull; acc[i][1] = 0ull; }

    // load coordinates
    const int ar0 = tid >> 2;            // A float4 id -> row (0..63), +64 for 2nd
    const int ac0 = (tid & 3) * 4;       // A col within BK
    const int br  = tid >> 4;            // B row within BK
    const int bc  = (tid & 15) * 4;      // B col within BN

    for (int k0 = 0; k0 < K; k0 += BK) {
        // A tile 128x16 -> transposed store
#pragma unroll
        for (int i = 0; i < 2; i++) {
            int r = ar0 + i * 64;
            float4 v = *(const float4*)&A[(m0 + r) * K + k0 + ac0];
            As[ac0 + 0][r] = v.x;
            As[ac0 + 1][r] = v.y;
            As[ac0 + 2][r] = v.z;
            As[ac0 + 3][r] = v.w;
        }
        // B tile 16x64 -> natural store
        {
            float4 v = *(const float4*)&W[(k0 + br) * N + n0 + bc];
            *(float4*)&Bs[br][bc] = v;
        }
        __syncthreads();

#pragma unroll
        for (int k = 0; k < BK; k++) {
            float4 a0 = *(float4*)&As[k][row];
            float4 a1 = *(float4*)&As[k][row + 4];
            float4 b  = *(float4*)&Bs[k][col];
            unsigned long long pb0 = pk2(b.x, b.y);
            unsigned long long pb1 = pk2(b.z, b.w);
            float av[8] = {a0.x, a0.y, a0.z, a0.w, a1.x, a1.y, a1.z, a1.w};
#pragma unroll
            for (int i = 0; i < 8; i++) {
                unsigned long long pa = pk2(av[i], av[i]);
                acc[i][0] = ffma2(pa, pb0, acc[i][0]);
                acc[i][1] = ffma2(pa, pb1, acc[i][1]);
            }
        }
        __syncthreads();
    }

    const float b0 = bias[n0 + col + 0];
    const float b1 = bias[n0 + col + 1];
    const float b2 = bias[n0 + col + 2];
    const float b3 = bias[n0 + col + 3];
#pragma unroll
    for (int i = 0; i < 8; i++) {
        float c0, c1, c2, c3;
        upk2(acc[i][0], c0, c1);
        upk2(acc[i][1], c2, c3);
        float4 o = make_float4(c0 + b0, c1 + b1, c2 + b2, c3 + b3);
        *(float4*)&C[(m0 + row + i) * N + n0 + col] = o;
    }
}

// ---------------- flash attention (per (b,h), 64-row Q tile) ----------------
// q,k,v layout: [L, B, DM] with head slice at h*64. Scale folded into Q load.
__global__ __launch_bounds__(256) void flash_attn(
    const float* __restrict__ q, const float* __restrict__ k,
    const float* __restrict__ v, const float* __restrict__ mask,
    float* __restrict__ ctx)
{
    __shared__ float Qst[DH * 64];  // [d][row]   (transposed)
    __shared__ float Kst[DH * 64];  // [d][col]   (transposed); reused as P [row][key]
    __shared__ float Vs[64 * DH];   // [key][d]   (natural)

    const int tid = threadIdx.x;
    const int tx = tid & 15;        // 16 over key/out cols
    const int ty = tid >> 4;        // 16 over q rows
    const int bh = blockIdx.y;
    const int b  = bh >> 3;
    const int h  = bh & 7;
    const int l0 = blockIdx.x * 64;
    const int hoff = h * DH;

    // Q tile load (scaled by 1/sqrt(64)), store transposed
#pragma unroll
    for (int i = 0; i < 4; i++) {
        int id = tid + i * 256;
        int r = id >> 4;
        int c = (id & 15) * 4;
        float4 w = *(const float4*)&q[((l0 + r) * NB + b) * DM + hoff + c];
        Qst[(c + 0) * 64 + r] = w.x * 0.125f;
        Qst[(c + 1) * 64 + r] = w.y * 0.125f;
        Qst[(c + 2) * 64 + r] = w.z * 0.125f;
        Qst[(c + 3) * 64 + r] = w.w * 0.125f;
    }

    unsigned long long O[4][2];
#pragma unroll
    for (int i = 0; i < 4; i++) { O[i][0] = 0ull; O[i][1] = 0ull; }
    float mrun[4], lrun[4];
#pragma unroll
    for (int i = 0; i < 4; i++) { mrun[i] = -1e30f; lrun[i] = 0.0f; }

    for (int t = 0; t < L_SEQ / 64; t++) {
        const int k0 = t * 64;
        // load K (transposed) and V (natural)
#pragma unroll
        for (int i = 0; i < 4; i++) {
            int id = tid + i * 256;
            int r = id >> 4;
            int c = (id & 15) * 4;
            float4 w = *(const float4*)&k[((k0 + r) * NB + b) * DM + hoff + c];
            Kst[(c + 0) * 64 + r] = w.x;
            Kst[(c + 1) * 64 + r] = w.y;
            Kst[(c + 2) * 64 + r] = w.z;
            Kst[(c + 3) * 64 + r] = w.w;
            float4 u = *(const float4*)&v[((k0 + r) * NB + b) * DM + hoff + c];
            *(float4*)&Vs[r * 64 + c] = u;
        }
        __syncthreads();

        // S = Qt @ Kt^T (scaled), packed over key-col pairs
        unsigned long long S[4][2];
#pragma unroll
        for (int i = 0; i < 4; i++) { S[i][0] = 0ull; S[i][1] = 0ull; }
#pragma unroll 8
        for (int d = 0; d < DH; d++) {
            float4 bb = *(float4*)&Kst[d * 64 + tx * 4];
            float4 aa = *(float4*)&Qst[d * 64 + ty * 4];
            unsigned long long pb0 = pk2(bb.x, bb.y);
            unsigned long long pb1 = pk2(bb.z, bb.w);
            float av[4] = {aa.x, aa.y, aa.z, aa.w};
#pragma unroll
            for (int i = 0; i < 4; i++) {
                unsigned long long pa = pk2(av[i], av[i]);
                S[i][0] = ffma2(pa, pb0, S[i][0]);
                S[i][1] = ffma2(pa, pb1, S[i][1]);
            }
        }

        // unpack, add mask, online softmax
        float s[4][4];
#pragma unroll
        for (int i = 0; i < 4; i++) {
            upk2(S[i][0], s[i][0], s[i][1]);
            upk2(S[i][1], s[i][2], s[i][3]);
            float4 mk = *(const float4*)&mask[(l0 + ty * 4 + i) * L_SEQ + k0 + tx * 4];
            s[i][0] += mk.x; s[i][1] += mk.y; s[i][2] += mk.z; s[i][3] += mk.w;
        }
        float p[4][4];
#pragma unroll
        for (int i = 0; i < 4; i++) {
            float mp = fmaxf(fmaxf(s[i][0], s[i][1]), fmaxf(s[i][2], s[i][3]));
#pragma unroll
            for (int o = 8; o >= 1; o >>= 1)
                mp = fmaxf(mp, __shfl_xor_sync(0xffffffffu, mp, o, 16));
            float mnew = fmaxf(mrun[i], mp);
            float alpha = __expf(mrun[i] - mnew);
            mrun[i] = mnew;
            float ls = 0.0f;
#pragma unroll
            for (int j = 0; j < 4; j++) { p[i][j] = __expf(s[i][j] - mnew); ls += p[i][j]; }
#pragma unroll
            for (int o = 8; o >= 1; o >>= 1)
                ls += __shfl_xor_sync(0xffffffffu, ls, o, 16);
            lrun[i] = lrun[i] * alpha + ls;
            unsigned long long pal = pk2(alpha, alpha);
            O[i][0] = fmul2(O[i][0], pal);
            O[i][1] = fmul2(O[i][1], pal);
        }
        __syncthreads();   // everyone finished reading Kst

        // write P into Kst buffer as [row][key]
#pragma unroll
        for (int i = 0; i < 4; i++) {
            float4 w = make_float4(p[i][0], p[i][1], p[i][2], p[i][3]);
            *(float4*)&Kst[(ty * 4 + i) * 64 + tx * 4] = w;
        }
        __syncthreads();

        // O += P @ V, packed over output-dim pairs
#pragma unroll 8
        for (int kk = 0; kk < 64; kk++) {
            float4 bb = *(float4*)&Vs[kk * 64 + tx * 4];
            unsigned long long pb0 = pk2(bb.x, bb.y);
            unsigned long long pb1 = pk2(bb.z, bb.w);
#pragma unroll
            for (int i = 0; i < 4; i++) {
                float a = Kst[(ty * 4 + i) * 64 + kk];
                unsigned long long pa = pk2(a, a);
                O[i][0] = ffma2(pa, pb0, O[i][0]);
                O[i][1] = ffma2(pa, pb1, O[i][1]);
            }
        }
        __syncthreads();   // before next tile overwrites Kst/Vs
    }

    // normalize + write context
#pragma unroll
    for (int i = 0; i < 4; i++) {
        float inv = 1.0f / lrun[i];
        float c0, c1, c2, c3;
        upk2(O[i][0], c0, c1);
        upk2(O[i][1], c2, c3);
        float4 o = make_float4(c0 * inv, c1 * inv, c2 * inv, c3 * inv);
        *(float4*)&ctx[((l0 + ty * 4 + i) * NB + b) * DM + hoff + tx * 4] = o;
    }
}

// ---------------- launch ----------------
extern "C" void kernel_launch(void* const* d_in, const int* in_sizes, int n_in,
                              void* d_out, int out_size) {
    (void)in_sizes; (void)n_in; (void)out_size;
    const float* Q    = (const float*)d_in[0];
    const float* K    = (const float*)d_in[1];
    const float* V    = (const float*)d_in[2];
    const float* mask = (const float*)d_in[3];
    const float* Wq   = (const float*)d_in[4];
    const float* bq   = (const float*)d_in[5];
    const float* Wk   = (const float*)d_in[6];
    const float* bk   = (const float*)d_in[7];
    const float* Wv   = (const float*)d_in[8];
    const float* bv   = (const float*)d_in[9];
    const float* Wo   = (const float*)d_in[10];
    const float* bo   = (const float*)d_in[11];
    float* out = (float*)d_out;

    float *pq, *pk, *pv, *pctx;
    cudaGetSymbolAddress((void**)&pq,   g_q);
    cudaGetSymbolAddress((void**)&pk,   g_k);
    cudaGetSymbolAddress((void**)&pv,   g_v);
    cudaGetSymbolAddress((void**)&pctx, g_ctx);

    dim3 gg(DM / BN, M_TOK / BM);   // (8, 64)
    sgemm_bias<<<gg, 256>>>(Q, Wq, bq, pq, M_TOK, DM, DM);
    sgemm_bias<<<gg, 256>>>(K, Wk, bk, pk, M_TOK, DM, DM);
    sgemm_bias<<<gg, 256>>>(V, Wv, bv, pv, M_TOK, DM, DM);

    dim3 ga(L_SEQ / 64, NB * NH);   // (16, 64)
    flash_attn<<<ga, 256>>>(pq, pk, pv, mask, pctx);

    sgemm_bias<<<gg, 256>>>(pctx, Wo, bo, out, M_TOK, DM, DM);
}

// round 4
// speedup vs baseline: 1.3721x; 1.3721x over previous
#include <cuda_runtime.h>
#include <cuda_bf16.h>
#include <cstdint>

// ---------------------------------------------------------------------------
// MultiHeadAttention.
// Projections + output GEMM: mma.sync bf16x3 (split fp32 -> hi/lo bf16,
//   C = Ah*Wh + Ah*Wl + Al*Wh via stacked K'=1536 bf16 GEMM, fp32 accum).
//   (tcgen05 unavailable: harness compiles PTX at compute_100, no 'a' features)
// Attention: fp32 SIMT flash kernel (unchanged from passing round).
// ---------------------------------------------------------------------------

#define L_SEQ 1024
#define NB    8
#define NH    8
#define DH    64
#define DM    512
#define M_TOK (L_SEQ * NB)   // 8192 tokens
#define K3    1536           // stacked K
#define NCH   24             // K3 / 64 chunks

// ---- scratch (device globals; allocation-free rule) ----
__device__ float g_q[M_TOK * DM];
__device__ float g_k[M_TOK * DM];
__device__ float g_v[M_TOK * DM];
__device__ float g_ctx[M_TOK * DM];
__device__ __nv_bfloat16 g_q3[M_TOK * K3];
__device__ __nv_bfloat16 g_k3[M_TOK * K3];
__device__ __nv_bfloat16 g_v3[M_TOK * K3];
__device__ __nv_bfloat16 g_c3[M_TOK * K3];
__device__ __nv_bfloat16 g_wq3[DM * K3];
__device__ __nv_bfloat16 g_wk3[DM * K3];
__device__ __nv_bfloat16 g_wv3[DM * K3];
__device__ __nv_bfloat16 g_wo3[DM * K3];

// =============================== PTX helpers ===============================
__device__ __forceinline__ uint32_t smem_u32(const void* p) {
    uint32_t a;
    asm("{ .reg .u64 t; cvta.to.shared.u64 t, %1; cvt.u32.u64 %0, t; }"
        : "=r"(a) : "l"(p));
    return a;
}
__device__ __forceinline__ void cp16(uint32_t dst, const void* src) {
    asm volatile("cp.async.cg.shared.global [%0], [%1], 16;" :: "r"(dst), "l"(src));
}
__device__ __forceinline__ void cp_commit() {
    asm volatile("cp.async.commit_group;" ::: "memory");
}
template <int N> __device__ __forceinline__ void cp_wait() {
    asm volatile("cp.async.wait_group %0;" :: "n"(N) : "memory");
}
__device__ __forceinline__ void ldsm4(uint32_t& r0, uint32_t& r1,
                                      uint32_t& r2, uint32_t& r3, uint32_t addr) {
    asm volatile("ldmatrix.sync.aligned.m8n8.x4.shared.b16 {%0,%1,%2,%3}, [%4];"
                 : "=r"(r0), "=r"(r1), "=r"(r2), "=r"(r3) : "r"(addr));
}
__device__ __forceinline__ void mma16816(float* d, uint32_t a0, uint32_t a1,
                                         uint32_t a2, uint32_t a3,
                                         uint32_t b0, uint32_t b1) {
    asm volatile(
        "mma.sync.aligned.m16n8k16.row.col.f32.bf16.bf16.f32 "
        "{%0,%1,%2,%3}, {%4,%5,%6,%7}, {%8,%9}, {%0,%1,%2,%3};"
        : "+f"(d[0]), "+f"(d[1]), "+f"(d[2]), "+f"(d[3])
        : "r"(a0), "r"(a1), "r"(a2), "r"(a3), "r"(b0), "r"(b1));
}
__device__ __forceinline__ uint32_t swz(uint32_t off) {
    return off ^ ((off >> 3) & 0x70);
}

// ---------------- packed f32x2 helpers (flash kernel) ----------------
__device__ __forceinline__ unsigned long long pk2(float lo, float hi) {
    unsigned long long r;
    asm("mov.b64 %0, {%1, %2};" : "=l"(r) : "f"(lo), "f"(hi));
    return r;
}
__device__ __forceinline__ void upk2(unsigned long long v, float& lo, float& hi) {
    asm("mov.b64 {%0, %1}, %2;" : "=f"(lo), "=f"(hi) : "l"(v));
}
__device__ __forceinline__ unsigned long long ffma2(unsigned long long a,
                                                    unsigned long long b,
                                                    unsigned long long c) {
    unsigned long long d;
    asm("fma.rn.f32x2 %0, %1, %2, %3;" : "=l"(d) : "l"(a), "l"(b), "l"(c));
    return d;
}
__device__ __forceinline__ unsigned long long fmul2(unsigned long long a,
                                                    unsigned long long b) {
    unsigned long long d;
    asm("mul.rn.f32x2 %0, %1, %2;" : "=l"(d) : "l"(a), "l"(b));
    return d;
}

// =============== split kernels: fp32 -> stacked bf16 hi/lo ===============
// A3[m, 0:512]=hi, [512:1024]=hi, [1024:1536]=lo
__global__ __launch_bounds__(256) void split_stack(const float* __restrict__ X,
                                                   __nv_bfloat16* __restrict__ Y) {
    int idx = blockIdx.x * 256 + threadIdx.x;      // M_TOK*128 threads
    int m = idx >> 7;
    int c = (idx & 127) * 4;
    float4 x = *(const float4*)&X[(size_t)m * DM + c];
    float xs[4] = {x.x, x.y, x.z, x.w};
    unsigned short hs[4], ls[4];
#pragma unroll
    for (int i = 0; i < 4; i++) {
        __nv_bfloat16 h = __float2bfloat16(xs[i]);
        __nv_bfloat16 l = __float2bfloat16(xs[i] - __bfloat162float(h));
        hs[i] = __bfloat16_as_ushort(h);
        ls[i] = __bfloat16_as_ushort(l);
    }
    uint2 hp = make_uint2((uint32_t)hs[0] | ((uint32_t)hs[1] << 16),
                          (uint32_t)hs[2] | ((uint32_t)hs[3] << 16));
    uint2 lp = make_uint2((uint32_t)ls[0] | ((uint32_t)ls[1] << 16),
                          (uint32_t)ls[2] | ((uint32_t)ls[3] << 16));
    __nv_bfloat16* y = Y + (size_t)m * K3 + c;
    *(uint2*)(y)        = hp;
    *(uint2*)(y + 512)  = hp;
    *(uint2*)(y + 1024) = lp;
}

// W [512(k), 512(n)] fp32 -> W3T [512(n), 1536(k')]: [Wh | Wl | Wh] (transposed)
__global__ __launch_bounds__(256) void split_w(const float* __restrict__ W,
                                               __nv_bfloat16* __restrict__ WT) {
    int idx = blockIdx.x * 256 + threadIdx.x;      // 512*512 threads
    int n = idx >> 9;
    int k = idx & 511;
    float x = W[(size_t)k * DM + n];
    __nv_bfloat16 h = __float2bfloat16(x);
    __nv_bfloat16 l = __float2bfloat16(x - __bfloat162float(h));
    __nv_bfloat16* y = WT + (size_t)n * K3;
    y[k] = h;
    y[512 + k] = l;
    y[1024 + k] = h;
}

// ================== mma.sync bf16 GEMM: C = A3 @ BT^T + bias ==================
// A3 [8192, 1536] bf16 row-major; BT [512, 1536] bf16 row-major (n-major rows,
// k contiguous == ".col" B operand layout).
// CTA tile 128x128, K-chunk 64; 8 warps as 2(m) x 4(n), warp tile 64x32.
// Double-buffered cp.async with SW128 swizzle; ldmatrix fragment loads.
#define GSMEM (1024 + 4 * 16384)

__global__ __launch_bounds__(256) void gemm_mma(const __nv_bfloat16* __restrict__ A,
                                                const __nv_bfloat16* __restrict__ BT,
                                                const float* __restrict__ bias,
                                                float* __restrict__ C) {
    extern __shared__ char smem_raw[];
    const uint32_t sbase = (smem_u32(smem_raw) + 1023) & ~1023u;
    const uint32_t SA[2] = {sbase,               sbase + 16384};
    const uint32_t SB[2] = {sbase + 2 * 16384,   sbase + 3 * 16384};

    const int tid  = threadIdx.x;
    const int lane = tid & 31;
    const int wid  = tid >> 5;
    const int wm   = wid >> 2;        // 0..1  -> 64 rows each
    const int wn   = wid & 3;         // 0..3  -> 32 cols each
    const int m0 = blockIdx.y * 128;
    const int n0 = blockIdx.x * 128;

    float acc[4][4][4];               // [m16 frag][n8 frag][4]
#pragma unroll
    for (int i = 0; i < 4; i++)
#pragma unroll
        for (int j = 0; j < 4; j++)
#pragma unroll
            for (int e = 0; e < 4; e++) acc[i][j][e] = 0.0f;

    // tile loader: 128 rows x 128B, SW128-swizzled, 4 cp.async 16B per thread
    auto load_tile = [&](uint32_t dst, const __nv_bfloat16* src, int row0, int k0) {
#pragma unroll
        for (int i = 0; i < 4; i++) {
            int idx = tid + i * 256;
            int r = idx >> 3;
            int sg = idx & 7;
            uint32_t d = dst + swz((uint32_t)(r * 128 + sg * 16));
            cp16(d, (const void*)(src + (size_t)(row0 + r) * K3 + k0 + sg * 8));
        }
    };

    // precomputed fragment smem offsets (pre-swizzle base parts)
    const int a_row = wm * 64 + (lane & 15);        // + i*16
    const int a_g16 = (lane >> 4) * 16;             // 0 or 16 bytes (k halves)
    const int b_row = wn * 32 + (lane & 7) + ((lane >> 4) << 3);   // + jj*16
    const int b_g16 = ((lane >> 3) & 1) * 16;

    load_tile(SA[0], A, m0, 0);
    load_tile(SB[0], BT, n0, 0);
    cp_commit();

    for (int c = 0; c < NCH; c++) {
        if (c + 1 < NCH) {
            load_tile(SA[(c + 1) & 1], A, m0, (c + 1) * 64);
            load_tile(SB[(c + 1) & 1], BT, n0, (c + 1) * 64);
            cp_commit();
            cp_wait<1>();             // chunk c's loads complete
        } else {
            cp_wait<0>();
        }
        __syncthreads();

        const uint32_t sa = SA[c & 1];
        const uint32_t sb = SB[c & 1];
#pragma unroll
        for (int kk = 0; kk < 4; kk++) {          // 4 x k16 within the 64-chunk
            uint32_t a[4][4];
#pragma unroll
            for (int i = 0; i < 4; i++) {
                uint32_t off = (uint32_t)((a_row + i * 16) * 128 + kk * 32 + a_g16);
                ldsm4(a[i][0], a[i][1], a[i][2], a[i][3], sa + swz(off));
            }
            uint32_t b[2][4];
#pragma unroll
            for (int jj = 0; jj < 2; jj++) {
                uint32_t off = (uint32_t)((b_row + jj * 16) * 128 + kk * 32 + b_g16);
                ldsm4(b[jj][0], b[jj][1], b[jj][2], b[jj][3], sb + swz(off));
            }
#pragma unroll
            for (int i = 0; i < 4; i++) {
#pragma unroll
                for (int j = 0; j < 4; j++) {
                    mma16816(acc[i][j], a[i][0], a[i][1], a[i][2], a[i][3],
                             b[j >> 1][(j & 1) * 2], b[j >> 1][(j & 1) * 2 + 1]);
                }
            }
        }
        __syncthreads();   // before next loads overwrite buffer c&1... (c+2)
    }

    // epilogue: bias + store fp32
#pragma unroll
    for (int i = 0; i < 4; i++) {
#pragma unroll
        for (int j = 0; j < 4; j++) {
            int r  = m0 + wm * 64 + i * 16 + (lane >> 2);
            int cc = n0 + wn * 32 + j * 8 + (lane & 3) * 2;
            float b0 = bias[cc], b1 = bias[cc + 1];
            float2 v0 = make_float2(acc[i][j][0] + b0, acc[i][j][1] + b1);
            float2 v1 = make_float2(acc[i][j][2] + b0, acc[i][j][3] + b1);
            *(float2*)&C[(size_t)r * DM + cc]       = v0;
            *(float2*)&C[(size_t)(r + 8) * DM + cc] = v1;
        }
    }
}

// ---------------- flash attention (unchanged, known correct) ----------------
__global__ __launch_bounds__(256) void flash_attn(
    const float* __restrict__ q, const float* __restrict__ k,
    const float* __restrict__ v, const float* __restrict__ mask,
    float* __restrict__ ctx)
{
    __shared__ float Qst[DH * 64];  // [d][row]   (transposed)
    __shared__ float Kst[DH * 64];  // [d][col]   (transposed); reused as P
    __shared__ float Vs[64 * DH];   // [key][d]

    const int tid = threadIdx.x;
    const int tx = tid & 15;
    const int ty = tid >> 4;
    const int bh = blockIdx.y;
    const int b  = bh >> 3;
    const int h  = bh & 7;
    const int l0 = blockIdx.x * 64;
    const int hoff = h * DH;

#pragma unroll
    for (int i = 0; i < 4; i++) {
        int id = tid + i * 256;
        int r = id >> 4;
        int c = (id & 15) * 4;
        float4 w = *(const float4*)&q[((l0 + r) * NB + b) * DM + hoff + c];
        Qst[(c + 0) * 64 + r] = w.x * 0.125f;
        Qst[(c + 1) * 64 + r] = w.y * 0.125f;
        Qst[(c + 2) * 64 + r] = w.z * 0.125f;
        Qst[(c + 3) * 64 + r] = w.w * 0.125f;
    }

    unsigned long long O[4][2];
#pragma unroll
    for (int i = 0; i < 4; i++) { O[i][0] = 0ull; O[i][1] = 0ull; }
    float mrun[4], lrun[4];
#pragma unroll
    for (int i = 0; i < 4; i++) { mrun[i] = -1e30f; lrun[i] = 0.0f; }

    for (int t = 0; t < L_SEQ / 64; t++) {
        const int k0 = t * 64;
#pragma unroll
        for (int i = 0; i < 4; i++) {
            int id = tid + i * 256;
            int r = id >> 4;
            int c = (id & 15) * 4;
            float4 w = *(const float4*)&k[((k0 + r) * NB + b) * DM + hoff + c];
            Kst[(c + 0) * 64 + r] = w.x;
            Kst[(c + 1) * 64 + r] = w.y;
            Kst[(c + 2) * 64 + r] = w.z;
            Kst[(c + 3) * 64 + r] = w.w;
            float4 u = *(const float4*)&v[((k0 + r) * NB + b) * DM + hoff + c];
            *(float4*)&Vs[r * 64 + c] = u;
        }
        __syncthreads();

        unsigned long long S[4][2];
#pragma unroll
        for (int i = 0; i < 4; i++) { S[i][0] = 0ull; S[i][1] = 0ull; }
#pragma unroll 8
        for (int d = 0; d < DH; d++) {
            float4 bb = *(float4*)&Kst[d * 64 + tx * 4];
            float4 aa = *(float4*)&Qst[d * 64 + ty * 4];
            unsigned long long pb0 = pk2(bb.x, bb.y);
            unsigned long long pb1 = pk2(bb.z, bb.w);
            float av[4] = {aa.x, aa.y, aa.z, aa.w};
#pragma unroll
            for (int i = 0; i < 4; i++) {
                unsigned long long pa = pk2(av[i], av[i]);
                S[i][0] = ffma2(pa, pb0, S[i][0]);
                S[i][1] = ffma2(pa, pb1, S[i][1]);
            }
        }

        float s[4][4];
#pragma unroll
        for (int i = 0; i < 4; i++) {
            upk2(S[i][0], s[i][0], s[i][1]);
            upk2(S[i][1], s[i][2], s[i][3]);
            float4 mk = *(const float4*)&mask[(l0 + ty * 4 + i) * L_SEQ + k0 + tx * 4];
            s[i][0] += mk.x; s[i][1] += mk.y; s[i][2] += mk.z; s[i][3] += mk.w;
        }
        float p[4][4];
#pragma unroll
        for (int i = 0; i < 4; i++) {
            float mp = fmaxf(fmaxf(s[i][0], s[i][1]), fmaxf(s[i][2], s[i][3]));
#pragma unroll
            for (int o = 8; o >= 1; o >>= 1)
                mp = fmaxf(mp, __shfl_xor_sync(0xffffffffu, mp, o, 16));
            float mnew = fmaxf(mrun[i], mp);
            float alpha = __expf(mrun[i] - mnew);
            mrun[i] = mnew;
            float ls = 0.0f;
#pragma unroll
            for (int j = 0; j < 4; j++) { p[i][j] = __expf(s[i][j] - mnew); ls += p[i][j]; }
#pragma unroll
            for (int o = 8; o >= 1; o >>= 1)
                ls += __shfl_xor_sync(0xffffffffu, ls, o, 16);
            lrun[i] = lrun[i] * alpha + ls;
            unsigned long long pal = pk2(alpha, alpha);
            O[i][0] = fmul2(O[i][0], pal);
            O[i][1] = fmul2(O[i][1], pal);
        }
        __syncthreads();

#pragma unroll
        for (int i = 0; i < 4; i++) {
            float4 w = make_float4(p[i][0], p[i][1], p[i][2], p[i][3]);
            *(float4*)&Kst[(ty * 4 + i) * 64 + tx * 4] = w;
        }
        __syncthreads();

#pragma unroll 8
        for (int kk = 0; kk < 64; kk++) {
            float4 bb = *(float4*)&Vs[kk * 64 + tx * 4];
            unsigned long long pb0 = pk2(bb.x, bb.y);
            unsigned long long pb1 = pk2(bb.z, bb.w);
#pragma unroll
            for (int i = 0; i < 4; i++) {
                float a = Kst[(ty * 4 + i) * 64 + kk];
                unsigned long long pa = pk2(a, a);
                O[i][0] = ffma2(pa, pb0, O[i][0]);
                O[i][1] = ffma2(pa, pb1, O[i][1]);
            }
        }
        __syncthreads();
    }

#pragma unroll
    for (int i = 0; i < 4; i++) {
        float inv = 1.0f / lrun[i];
        float c0, c1, c2, c3;
        upk2(O[i][0], c0, c1);
        upk2(O[i][1], c2, c3);
        float4 o = make_float4(c0 * inv, c1 * inv, c2 * inv, c3 * inv);
        *(float4*)&ctx[((l0 + ty * 4 + i) * NB + b) * DM + hoff + tx * 4] = o;
    }
}

// ---------------- launch ----------------
extern "C" void kernel_launch(void* const* d_in, const int* in_sizes, int n_in,
                              void* d_out, int out_size) {
    (void)in_sizes; (void)n_in; (void)out_size;
    const float* Q    = (const float*)d_in[0];
    const float* K    = (const float*)d_in[1];
    const float* V    = (const float*)d_in[2];
    const float* mask = (const float*)d_in[3];
    const float* Wq   = (const float*)d_in[4];
    const float* bq   = (const float*)d_in[5];
    const float* Wk   = (const float*)d_in[6];
    const float* bk   = (const float*)d_in[7];
    const float* Wv   = (const float*)d_in[8];
    const float* bv   = (const float*)d_in[9];
    const float* Wo   = (const float*)d_in[10];
    const float* bo   = (const float*)d_in[11];
    float* out = (float*)d_out;

    float *pq, *pk, *pv, *pctx;
    __nv_bfloat16 *pq3, *pk3, *pv3, *pc3, *pwq3, *pwk3, *pwv3, *pwo3;
    cudaGetSymbolAddress((void**)&pq,   g_q);
    cudaGetSymbolAddress((void**)&pk,   g_k);
    cudaGetSymbolAddress((void**)&pv,   g_v);
    cudaGetSymbolAddress((void**)&pctx, g_ctx);
    cudaGetSymbolAddress((void**)&pq3,  g_q3);
    cudaGetSymbolAddress((void**)&pk3,  g_k3);
    cudaGetSymbolAddress((void**)&pv3,  g_v3);
    cudaGetSymbolAddress((void**)&pc3,  g_c3);
    cudaGetSymbolAddress((void**)&pwq3, g_wq3);
    cudaGetSymbolAddress((void**)&pwk3, g_wk3);
    cudaGetSymbolAddress((void**)&pwv3, g_wv3);
    cudaGetSymbolAddress((void**)&pwo3, g_wo3);

    cudaFuncSetAttribute(gemm_mma, cudaFuncAttributeMaxDynamicSharedMemorySize, GSMEM);

    // weight splits (small)
    split_w<<<1024, 256>>>(Wq, pwq3);
    split_w<<<1024, 256>>>(Wk, pwk3);
    split_w<<<1024, 256>>>(Wv, pwv3);
    split_w<<<1024, 256>>>(Wo, pwo3);

    // activation splits
    split_stack<<<4096, 256>>>(Q, pq3);
    split_stack<<<4096, 256>>>(K, pk3);
    split_stack<<<4096, 256>>>(V, pv3);

    dim3 gg(DM / 128, M_TOK / 128);   // (4, 64)
    gemm_mma<<<gg, 256, GSMEM>>>(pq3, pwq3, bq, pq);
    gemm_mma<<<gg, 256, GSMEM>>>(pk3, pwk3, bk, pk);
    gemm_mma<<<gg, 256, GSMEM>>>(pv3, pwv3, bv, pv);

    dim3 ga(L_SEQ / 64, NB * NH);     // (16, 64)
    flash_attn<<<ga, 256>>>(pq, pk, pv, mask, pctx);

    split_stack<<<4096, 256>>>(pctx, pc3);
    gemm_mma<<<gg, 256, GSMEM>>>(pc3, pwo3, bo, out);
}

// round 5
// speedup vs baseline: 2.4172x; 1.7616x over previous
#include <cuda_runtime.h>
#include <cuda_bf16.h>
#include <cstdint>

// ---------------------------------------------------------------------------
// MultiHeadAttention, fully tensor-core (mma.sync bf16x3, fp32 accum):
//  - 4 projection/output GEMMs: stacked-K bf16x3 (unchanged from R4).
//  - Attention: mma.sync flash kernel; S and P@V both bf16x3.
//  (tcgen05 unavailable: harness compiles PTX at compute_100.)
// ---------------------------------------------------------------------------

#define L_SEQ 1024
#define NB    8
#define NH    8
#define DH    64
#define DM    512
#define M_TOK (L_SEQ * NB)
#define K3    1536
#define NCH   24

// ---- scratch ----
__device__ float g_q[M_TOK * DM];
__device__ float g_k[M_TOK * DM];
__device__ float g_v[M_TOK * DM];
__device__ float g_ctx[M_TOK * DM];
__device__ __nv_bfloat16 g_q3[M_TOK * K3];
__device__ __nv_bfloat16 g_k3[M_TOK * K3];
__device__ __nv_bfloat16 g_v3[M_TOK * K3];
__device__ __nv_bfloat16 g_c3[M_TOK * K3];
__device__ __nv_bfloat16 g_wq3[DM * K3];
__device__ __nv_bfloat16 g_wk3[DM * K3];
__device__ __nv_bfloat16 g_wv3[DM * K3];
__device__ __nv_bfloat16 g_wo3[DM * K3];
// attention operands: [bh][l][d] hi/lo and transposed V [bh][d][l]
__device__ __nv_bfloat16 g_qh[64 * L_SEQ * DH];
__device__ __nv_bfloat16 g_ql[64 * L_SEQ * DH];
__device__ __nv_bfloat16 g_kh[64 * L_SEQ * DH];
__device__ __nv_bfloat16 g_kl[64 * L_SEQ * DH];
__device__ __nv_bfloat16 g_vth[64 * DH * L_SEQ];
__device__ __nv_bfloat16 g_vtl[64 * DH * L_SEQ];

// =============================== PTX helpers ===============================
__device__ __forceinline__ uint32_t smem_u32(const void* p) {
    uint32_t a;
    asm("{ .reg .u64 t; cvta.to.shared.u64 t, %1; cvt.u32.u64 %0, t; }"
        : "=r"(a) : "l"(p));
    return a;
}
__device__ __forceinline__ void cp16(uint32_t dst, const void* src) {
    asm volatile("cp.async.cg.shared.global [%0], [%1], 16;" :: "r"(dst), "l"(src));
}
__device__ __forceinline__ void cp_commit() {
    asm volatile("cp.async.commit_group;" ::: "memory");
}
template <int N> __device__ __forceinline__ void cp_wait() {
    asm volatile("cp.async.wait_group %0;" :: "n"(N) : "memory");
}
__device__ __forceinline__ void ldsm4(uint32_t& r0, uint32_t& r1,
                                      uint32_t& r2, uint32_t& r3, uint32_t addr) {
    asm volatile("ldmatrix.sync.aligned.m8n8.x4.shared.b16 {%0,%1,%2,%3}, [%4];"
                 : "=r"(r0), "=r"(r1), "=r"(r2), "=r"(r3) : "r"(addr));
}
__device__ __forceinline__ void mma16816(float* d, uint32_t a0, uint32_t a1,
                                         uint32_t a2, uint32_t a3,
                                         uint32_t b0, uint32_t b1) {
    asm volatile(
        "mma.sync.aligned.m16n8k16.row.col.f32.bf16.bf16.f32 "
        "{%0,%1,%2,%3}, {%4,%5,%6,%7}, {%8,%9}, {%0,%1,%2,%3};"
        : "+f"(d[0]), "+f"(d[1]), "+f"(d[2]), "+f"(d[3])
        : "r"(a0), "r"(a1), "r"(a2), "r"(a3), "r"(b0), "r"(b1));
}
__device__ __forceinline__ uint32_t swz(uint32_t off) {
    return off ^ ((off >> 3) & 0x70);
}
// pack two f32 -> bf16x2 {hi, lo}
__device__ __forceinline__ uint32_t cvt2bf(float hi, float lo) {
    uint32_t r;
    asm("cvt.rn.bf16x2.f32 %0, %1, %2;" : "=r"(r) : "f"(hi), "f"(lo));
    return r;
}

// =============== split kernels: fp32 -> stacked bf16 hi/lo ===============
__global__ __launch_bounds__(256) void split_stack(const float* __restrict__ X,
                                                   __nv_bfloat16* __restrict__ Y) {
    int idx = blockIdx.x * 256 + threadIdx.x;
    int m = idx >> 7;
    int c = (idx & 127) * 4;
    float4 x = *(const float4*)&X[(size_t)m * DM + c];
    float xs[4] = {x.x, x.y, x.z, x.w};
    unsigned short hs[4], ls[4];
#pragma unroll
    for (int i = 0; i < 4; i++) {
        __nv_bfloat16 h = __float2bfloat16(xs[i]);
        __nv_bfloat16 l = __float2bfloat16(xs[i] - __bfloat162float(h));
        hs[i] = __bfloat16_as_ushort(h);
        ls[i] = __bfloat16_as_ushort(l);
    }
    uint2 hp = make_uint2((uint32_t)hs[0] | ((uint32_t)hs[1] << 16),
                          (uint32_t)hs[2] | ((uint32_t)hs[3] << 16));
    uint2 lp = make_uint2((uint32_t)ls[0] | ((uint32_t)ls[1] << 16),
                          (uint32_t)ls[2] | ((uint32_t)ls[3] << 16));
    __nv_bfloat16* y = Y + (size_t)m * K3 + c;
    *(uint2*)(y)        = hp;
    *(uint2*)(y + 512)  = hp;
    *(uint2*)(y + 1024) = lp;
}

__global__ __launch_bounds__(256) void split_w(const float* __restrict__ W,
                                               __nv_bfloat16* __restrict__ WT) {
    int idx = blockIdx.x * 256 + threadIdx.x;
    int n = idx >> 9;
    int k = idx & 511;
    float x = W[(size_t)k * DM + n];
    __nv_bfloat16 h = __float2bfloat16(x);
    __nv_bfloat16 l = __float2bfloat16(x - __bfloat162float(h));
    __nv_bfloat16* y = WT + (size_t)n * K3;
    y[k] = h;
    y[512 + k] = l;
    y[1024 + k] = h;
}

// ====== attention preps: [l,b,h*64+d] fp32 -> [bh][l][d] bf16 hi/lo ======
__global__ __launch_bounds__(256) void prep_qk(const float* __restrict__ X,
                                               __nv_bfloat16* __restrict__ XH,
                                               __nv_bfloat16* __restrict__ XL,
                                               float scale) {
    int tg = blockIdx.x * 256 + threadIdx.x;   // 1,048,576 threads, 4 d each
    int d4 = (tg & 15) * 4;
    int l  = (tg >> 4) & 1023;
    int bh = tg >> 14;
    int b = bh >> 3, h = bh & 7;
    float4 x = *(const float4*)&X[((size_t)l * NB + b) * DM + h * 64 + d4];
    float xs[4] = {x.x * scale, x.y * scale, x.z * scale, x.w * scale};
    unsigned short hs[4], ls[4];
#pragma unroll
    for (int i = 0; i < 4; i++) {
        __nv_bfloat16 hh = __float2bfloat16(xs[i]);
        __nv_bfloat16 ll = __float2bfloat16(xs[i] - __bfloat162float(hh));
        hs[i] = __bfloat16_as_ushort(hh);
        ls[i] = __bfloat16_as_ushort(ll);
    }
    size_t o = ((size_t)bh * 1024 + l) * 64 + d4;
    *(uint2*)&XH[o] = make_uint2((uint32_t)hs[0] | ((uint32_t)hs[1] << 16),
                                 (uint32_t)hs[2] | ((uint32_t)hs[3] << 16));
    *(uint2*)&XL[o] = make_uint2((uint32_t)ls[0] | ((uint32_t)ls[1] << 16),
                                 (uint32_t)ls[2] | ((uint32_t)ls[3] << 16));
}

// V transpose-split: [l,b,h*64+d] fp32 -> [bh][d][l] bf16 hi/lo
__global__ __launch_bounds__(256) void prep_vt(const float* __restrict__ V,
                                               __nv_bfloat16* __restrict__ VTH,
                                               __nv_bfloat16* __restrict__ VTL) {
    __shared__ float t[64][65];
    int bh = blockIdx.y;
    int b = bh >> 3, h = bh & 7;
    int l0 = blockIdx.x * 64;
    int tid = threadIdx.x;
#pragma unroll
    for (int i = 0; i < 16; i++) {
        int idx = i * 256 + tid;
        int r = idx >> 6, c = idx & 63;
        t[r][c] = V[((size_t)(l0 + r) * NB + b) * DM + h * 64 + c];
    }
    __syncthreads();
#pragma unroll
    for (int i = 0; i < 16; i++) {
        int idx = i * 256 + tid;
        int d = idx >> 6, l = idx & 63;
        float x = t[l][d];
        __nv_bfloat16 hh = __float2bfloat16(x);
        __nv_bfloat16 ll = __float2bfloat16(x - __bfloat162float(hh));
        size_t o = ((size_t)bh * 64 + d) * 1024 + l0 + l;
        VTH[o] = hh;
        VTL[o] = ll;
    }
}

// ================== mma.sync bf16 GEMM (unchanged from R4) ==================
#define GSMEM (1024 + 4 * 16384)

__global__ __launch_bounds__(256) void gemm_mma(const __nv_bfloat16* __restrict__ A,
                                                const __nv_bfloat16* __restrict__ BT,
                                                const float* __restrict__ bias,
                                                float* __restrict__ C) {
    extern __shared__ char smem_raw[];
    const uint32_t sbase = (smem_u32(smem_raw) + 1023) & ~1023u;
    const uint32_t SA[2] = {sbase,               sbase + 16384};
    const uint32_t SB[2] = {sbase + 2 * 16384,   sbase + 3 * 16384};

    const int tid  = threadIdx.x;
    const int lane = tid & 31;
    const int wid  = tid >> 5;
    const int wm   = wid >> 2;
    const int wn   = wid & 3;
    const int m0 = blockIdx.y * 128;
    const int n0 = blockIdx.x * 128;

    float acc[4][4][4];
#pragma unroll
    for (int i = 0; i < 4; i++)
#pragma unroll
        for (int j = 0; j < 4; j++)
#pragma unroll
            for (int e = 0; e < 4; e++) acc[i][j][e] = 0.0f;

    auto load_tile = [&](uint32_t dst, const __nv_bfloat16* src, int row0, int k0) {
#pragma unroll
        for (int i = 0; i < 4; i++) {
            int idx = tid + i * 256;
            int r = idx >> 3;
            int sg = idx & 7;
            uint32_t d = dst + swz((uint32_t)(r * 128 + sg * 16));
            cp16(d, (const void*)(src + (size_t)(row0 + r) * K3 + k0 + sg * 8));
        }
    };

    const int a_row = wm * 64 + (lane & 15);
    const int a_g16 = (lane >> 4) * 16;
    const int b_row = wn * 32 + (lane & 7) + ((lane >> 4) << 3);
    const int b_g16 = ((lane >> 3) & 1) * 16;

    load_tile(SA[0], A, m0, 0);
    load_tile(SB[0], BT, n0, 0);
    cp_commit();

    for (int c = 0; c < NCH; c++) {
        if (c + 1 < NCH) {
            load_tile(SA[(c + 1) & 1], A, m0, (c + 1) * 64);
            load_tile(SB[(c + 1) & 1], BT, n0, (c + 1) * 64);
            cp_commit();
            cp_wait<1>();
        } else {
            cp_wait<0>();
        }
        __syncthreads();

        const uint32_t sa = SA[c & 1];
        const uint32_t sb = SB[c & 1];
#pragma unroll
        for (int kk = 0; kk < 4; kk++) {
            uint32_t a[4][4];
#pragma unroll
            for (int i = 0; i < 4; i++) {
                uint32_t off = (uint32_t)((a_row + i * 16) * 128 + kk * 32 + a_g16);
                ldsm4(a[i][0], a[i][1], a[i][2], a[i][3], sa + swz(off));
            }
            uint32_t b[2][4];
#pragma unroll
            for (int jj = 0; jj < 2; jj++) {
                uint32_t off = (uint32_t)((b_row + jj * 16) * 128 + kk * 32 + b_g16);
                ldsm4(b[jj][0], b[jj][1], b[jj][2], b[jj][3], sb + swz(off));
            }
#pragma unroll
            for (int i = 0; i < 4; i++) {
#pragma unroll
                for (int j = 0; j < 4; j++) {
                    mma16816(acc[i][j], a[i][0], a[i][1], a[i][2], a[i][3],
                             b[j >> 1][(j & 1) * 2], b[j >> 1][(j & 1) * 2 + 1]);
                }
            }
        }
        __syncthreads();
    }

#pragma unroll
    for (int i = 0; i < 4; i++) {
#pragma unroll
        for (int j = 0; j < 4; j++) {
            int r  = m0 + wm * 64 + i * 16 + (lane >> 2);
            int cc = n0 + wn * 32 + j * 8 + (lane & 3) * 2;
            float b0 = bias[cc], b1 = bias[cc + 1];
            float2 v0 = make_float2(acc[i][j][0] + b0, acc[i][j][1] + b1);
            float2 v1 = make_float2(acc[i][j][2] + b0, acc[i][j][3] + b1);
            *(float2*)&C[(size_t)r * DM + cc]       = v0;
            *(float2*)&C[(size_t)(r + 8) * DM + cc] = v1;
        }
    }
}

// ============ flash attention, mma.sync bf16x3 both GEMMs ============
// CTA: 128 q rows of one (b,h). 8 warps x m16. 16 key tiles of 64 keys,
// double-buffered cp.async (Kh,Kl,Vth,Vtl 8KB each). Softmax fp32 in regs.
#define FSMEM (1024 + 96 * 1024)

__global__ __launch_bounds__(256) void flash_mma(
    const __nv_bfloat16* __restrict__ qh, const __nv_bfloat16* __restrict__ ql,
    const __nv_bfloat16* __restrict__ kh, const __nv_bfloat16* __restrict__ kl,
    const __nv_bfloat16* __restrict__ vth, const __nv_bfloat16* __restrict__ vtl,
    const float* __restrict__ mask, float* __restrict__ ctx)
{
    extern __shared__ char smem_raw[];
    const uint32_t sbase = (smem_u32(smem_raw) + 1023) & ~1023u;
    const uint32_t QH = sbase, QL = sbase + 16384;
    const uint32_t BUF = sbase + 32768;   // + bb*32768 + {KH:0,KL:8K,VH:16K,VL:24K}

    const int tid = threadIdx.x, lane = tid & 31, wid = tid >> 5;
    const int bh = blockIdx.y;
    const int bb_ = bh >> 3, hh_ = bh & 7;
    const int l0 = blockIdx.x * 128;
    const size_t qoff = ((size_t)bh * 1024 + l0) * 64;
    const size_t koff = (size_t)bh * 1024 * 64;
    const size_t voff = (size_t)bh * 64 * 1024;

    // Q tiles (Qh, Ql): 128 rows x 128B
#pragma unroll
    for (int i = 0; i < 4; i++) {
        int idx = tid + i * 256;
        int r = idx >> 3, sg = idx & 7;
        uint32_t so = swz((uint32_t)(r * 128 + sg * 16));
        cp16(QH + so, (const void*)(qh + qoff + (size_t)r * 64 + sg * 8));
        cp16(QL + so, (const void*)(ql + qoff + (size_t)r * 64 + sg * 8));
    }
    cp_commit();

    auto load_kv = [&](int bb, int t) {
        const uint32_t base = BUF + bb * 32768;
#pragma unroll
        for (int i = 0; i < 2; i++) {
            int idx = tid + i * 256;
            int r = idx >> 3, sg = idx & 7;
            uint32_t so = swz((uint32_t)(r * 128 + sg * 16));
            cp16(base         + so, (const void*)(kh  + koff + (size_t)(t * 64 + r) * 64 + sg * 8));
            cp16(base + 8192  + so, (const void*)(kl  + koff + (size_t)(t * 64 + r) * 64 + sg * 8));
            cp16(base + 16384 + so, (const void*)(vth + voff + (size_t)r * 1024 + t * 64 + sg * 8));
            cp16(base + 24576 + so, (const void*)(vtl + voff + (size_t)r * 1024 + t * 64 + sg * 8));
        }
    };
    load_kv(0, 0);
    cp_commit();
    cp_wait<0>();
    __syncthreads();

    // persistent Q fragments
    uint32_t Qh[4][4], Ql[4][4];
    {
        const int a_row = wid * 16 + (lane & 15);
        const uint32_t g16 = (uint32_t)((lane >> 4) * 16);
#pragma unroll
        for (int kk = 0; kk < 4; kk++) {
            uint32_t off = swz((uint32_t)(a_row * 128 + kk * 32) + g16);
            ldsm4(Qh[kk][0], Qh[kk][1], Qh[kk][2], Qh[kk][3], QH + off);
            ldsm4(Ql[kk][0], Ql[kk][1], Ql[kk][2], Ql[kk][3], QL + off);
        }
    }

    const int b_row = (lane & 7) + ((lane >> 4) << 3);
    const uint32_t b_g16 = (uint32_t)(((lane >> 3) & 1) * 16);

    float O[8][4];
#pragma unroll
    for (int j = 0; j < 8; j++)
#pragma unroll
        for (int e = 0; e < 4; e++) O[j][e] = 0.0f;
    float mrow0 = -1e30f, mrow1 = -1e30f, lrow0 = 0.0f, lrow1 = 0.0f;

    const int rq0 = l0 + wid * 16 + (lane >> 2);
    const int colq = (lane & 3) * 2;

    for (int t = 0; t < 16; t++) {
        if (t + 1 < 16) {
            load_kv((t + 1) & 1, t + 1);
            cp_commit();
            cp_wait<1>();
        } else {
            cp_wait<0>();
        }
        __syncthreads();
        const uint32_t base = BUF + (t & 1) * 32768;

        // ---- S = Qh*Kh + Qh*Kl + Ql*Kh ----
        float S[8][4];
#pragma unroll
        for (int j = 0; j < 8; j++)
#pragma unroll
            for (int e = 0; e < 4; e++) S[j][e] = 0.0f;
#pragma unroll
        for (int kk = 0; kk < 4; kk++) {
            uint32_t bH[4][4], bL[4][4];
#pragma unroll
            for (int jj = 0; jj < 4; jj++) {
                uint32_t off = swz((uint32_t)((b_row + jj * 16) * 128 + kk * 32) + b_g16);
                ldsm4(bH[jj][0], bH[jj][1], bH[jj][2], bH[jj][3], base + off);
                ldsm4(bL[jj][0], bL[jj][1], bL[jj][2], bL[jj][3], base + 8192 + off);
            }
#pragma unroll
            for (int j = 0; j < 8; j++) {
                uint32_t h0 = bH[j >> 1][(j & 1) * 2], h1 = bH[j >> 1][(j & 1) * 2 + 1];
                uint32_t u0 = bL[j >> 1][(j & 1) * 2], u1 = bL[j >> 1][(j & 1) * 2 + 1];
                mma16816(S[j], Qh[kk][0], Qh[kk][1], Qh[kk][2], Qh[kk][3], h0, h1);
                mma16816(S[j], Qh[kk][0], Qh[kk][1], Qh[kk][2], Qh[kk][3], u0, u1);
                mma16816(S[j], Ql[kk][0], Ql[kk][1], Ql[kk][2], Ql[kk][3], h0, h1);
            }
        }

        // ---- mask + online softmax (rows rq0, rq0+8) ----
        const int kc = t * 64;
#pragma unroll
        for (int j = 0; j < 8; j++) {
            float2 m0 = *(const float2*)&mask[(size_t)rq0 * L_SEQ + kc + j * 8 + colq];
            float2 m1 = *(const float2*)&mask[(size_t)(rq0 + 8) * L_SEQ + kc + j * 8 + colq];
            S[j][0] += m0.x; S[j][1] += m0.y;
            S[j][2] += m1.x; S[j][3] += m1.y;
        }
        float mx0 = -1e30f, mx1 = -1e30f;
#pragma unroll
        for (int j = 0; j < 8; j++) {
            mx0 = fmaxf(mx0, fmaxf(S[j][0], S[j][1]));
            mx1 = fmaxf(mx1, fmaxf(S[j][2], S[j][3]));
        }
        mx0 = fmaxf(mx0, __shfl_xor_sync(0xffffffffu, mx0, 1));
        mx0 = fmaxf(mx0, __shfl_xor_sync(0xffffffffu, mx0, 2));
        mx1 = fmaxf(mx1, __shfl_xor_sync(0xffffffffu, mx1, 1));
        mx1 = fmaxf(mx1, __shfl_xor_sync(0xffffffffu, mx1, 2));
        float mn0 = fmaxf(mrow0, mx0), mn1 = fmaxf(mrow1, mx1);
        float al0 = __expf(mrow0 - mn0), al1 = __expf(mrow1 - mn1);
        mrow0 = mn0; mrow1 = mn1;
        float s0 = 0.0f, s1 = 0.0f;
#pragma unroll
        for (int j = 0; j < 8; j++) {
            S[j][0] = __expf(S[j][0] - mn0);
            S[j][1] = __expf(S[j][1] - mn0);
            S[j][2] = __expf(S[j][2] - mn1);
            S[j][3] = __expf(S[j][3] - mn1);
            s0 += S[j][0] + S[j][1];
            s1 += S[j][2] + S[j][3];
        }
        s0 += __shfl_xor_sync(0xffffffffu, s0, 1);
        s0 += __shfl_xor_sync(0xffffffffu, s0, 2);
        s1 += __shfl_xor_sync(0xffffffffu, s1, 1);
        s1 += __shfl_xor_sync(0xffffffffu, s1, 2);
        lrow0 = lrow0 * al0 + s0;
        lrow1 = lrow1 * al1 + s1;
#pragma unroll
        for (int j = 0; j < 8; j++) {
            O[j][0] *= al0; O[j][1] *= al0;
            O[j][2] *= al1; O[j][3] *= al1;
        }

        // ---- P fragments (register-only): Ph = bf16(p), Pl = p - Ph ----
        uint32_t Ph[4][4], Pl[4][4];
#pragma unroll
        for (int kk = 0; kk < 4; kk++) {
            const int j0 = 2 * kk, j1 = 2 * kk + 1;
            Ph[kk][0] = cvt2bf(S[j0][1], S[j0][0]);
            Ph[kk][1] = cvt2bf(S[j0][3], S[j0][2]);
            Ph[kk][2] = cvt2bf(S[j1][1], S[j1][0]);
            Ph[kk][3] = cvt2bf(S[j1][3], S[j1][2]);
#pragma unroll
            for (int e = 0; e < 4; e++) {
                const int jj = (e < 2) ? j0 : j1;
                const int lo = (e & 1) * 2;   // element index of low slot
                float plo = S[jj][lo]     - __uint_as_float(Ph[kk][e] << 16);
                float phi = S[jj][lo + 1] - __uint_as_float(Ph[kk][e] & 0xffff0000u);
                Pl[kk][e] = cvt2bf(phi, plo);
            }
        }

        // ---- O += Ph*Vh + Ph*Vl + Pl*Vh ----
#pragma unroll
        for (int kk = 0; kk < 4; kk++) {
            uint32_t vH[4][4], vL[4][4];
#pragma unroll
            for (int jj = 0; jj < 4; jj++) {
                uint32_t off = swz((uint32_t)((b_row + jj * 16) * 128 + kk * 32) + b_g16);
                ldsm4(vH[jj][0], vH[jj][1], vH[jj][2], vH[jj][3], base + 16384 + off);
                ldsm4(vL[jj][0], vL[jj][1], vL[jj][2], vL[jj][3], base + 24576 + off);
            }
#pragma unroll
            for (int j = 0; j < 8; j++) {
                uint32_t h0 = vH[j >> 1][(j & 1) * 2], h1 = vH[j >> 1][(j & 1) * 2 + 1];
                uint32_t u0 = vL[j >> 1][(j & 1) * 2], u1 = vL[j >> 1][(j & 1) * 2 + 1];
                mma16816(O[j], Ph[kk][0], Ph[kk][1], Ph[kk][2], Ph[kk][3], h0, h1);
                mma16816(O[j], Ph[kk][0], Ph[kk][1], Ph[kk][2], Ph[kk][3], u0, u1);
                mma16816(O[j], Pl[kk][0], Pl[kk][1], Pl[kk][2], Pl[kk][3], h0, h1);
            }
        }
        __syncthreads();
    }

    // ---- normalize + store ctx ----
    const float inv0 = 1.0f / lrow0, inv1 = 1.0f / lrow1;
#pragma unroll
    for (int j = 0; j < 8; j++) {
        int cc = hh_ * 64 + j * 8 + colq;
        float2 v0 = make_float2(O[j][0] * inv0, O[j][1] * inv0);
        float2 v1 = make_float2(O[j][2] * inv1, O[j][3] * inv1);
        *(float2*)&ctx[((size_t)rq0 * NB + bb_) * DM + cc]       = v0;
        *(float2*)&ctx[((size_t)(rq0 + 8) * NB + bb_) * DM + cc] = v1;
    }
}

// ---------------- launch ----------------
extern "C" void kernel_launch(void* const* d_in, const int* in_sizes, int n_in,
                              void* d_out, int out_size) {
    (void)in_sizes; (void)n_in; (void)out_size;
    const float* Q    = (const float*)d_in[0];
    const float* K    = (const float*)d_in[1];
    const float* V    = (const float*)d_in[2];
    const float* mask = (const float*)d_in[3];
    const float* Wq   = (const float*)d_in[4];
    const float* bq   = (const float*)d_in[5];
    const float* Wk   = (const float*)d_in[6];
    const float* bk   = (const float*)d_in[7];
    const float* Wv   = (const float*)d_in[8];
    const float* bv   = (const float*)d_in[9];
    const float* Wo   = (const float*)d_in[10];
    const float* bo   = (const float*)d_in[11];
    float* out = (float*)d_out;

    float *pq, *pk, *pv, *pctx;
    __nv_bfloat16 *pq3, *pk3, *pv3, *pc3, *pwq3, *pwk3, *pwv3, *pwo3;
    __nv_bfloat16 *pqh, *pql, *pkh, *pkl, *pvth, *pvtl;
    cudaGetSymbolAddress((void**)&pq,   g_q);
    cudaGetSymbolAddress((void**)&pk,   g_k);
    cudaGetSymbolAddress((void**)&pv,   g_v);
    cudaGetSymbolAddress((void**)&pctx, g_ctx);
    cudaGetSymbolAddress((void**)&pq3,  g_q3);
    cudaGetSymbolAddress((void**)&pk3,  g_k3);
    cudaGetSymbolAddress((void**)&pv3,  g_v3);
    cudaGetSymbolAddress((void**)&pc3,  g_c3);
    cudaGetSymbolAddress((void**)&pwq3, g_wq3);
    cudaGetSymbolAddress((void**)&pwk3, g_wk3);
    cudaGetSymbolAddress((void**)&pwv3, g_wv3);
    cudaGetSymbolAddress((void**)&pwo3, g_wo3);
    cudaGetSymbolAddress((void**)&pqh,  g_qh);
    cudaGetSymbolAddress((void**)&pql,  g_ql);
    cudaGetSymbolAddress((void**)&pkh,  g_kh);
    cudaGetSymbolAddress((void**)&pkl,  g_kl);
    cudaGetSymbolAddress((void**)&pvth, g_vth);
    cudaGetSymbolAddress((void**)&pvtl, g_vtl);

    cudaFuncSetAttribute(gemm_mma, cudaFuncAttributeMaxDynamicSharedMemorySize, GSMEM);
    cudaFuncSetAttribute(flash_mma, cudaFuncAttributeMaxDynamicSharedMemorySize, FSMEM);

    split_w<<<1024, 256>>>(Wq, pwq3);
    split_w<<<1024, 256>>>(Wk, pwk3);
    split_w<<<1024, 256>>>(Wv, pwv3);
    split_w<<<1024, 256>>>(Wo, pwo3);

    split_stack<<<4096, 256>>>(Q, pq3);
    split_stack<<<4096, 256>>>(K, pk3);
    split_stack<<<4096, 256>>>(V, pv3);

    dim3 gg(DM / 128, M_TOK / 128);   // (4, 64)
    gemm_mma<<<gg, 256, GSMEM>>>(pq3, pwq3, bq, pq);
    gemm_mma<<<gg, 256, GSMEM>>>(pk3, pwk3, bk, pk);
    gemm_mma<<<gg, 256, GSMEM>>>(pv3, pwv3, bv, pv);

    prep_qk<<<4096, 256>>>(pq, pqh, pql, 0.125f);
    prep_qk<<<4096, 256>>>(pk, pkh, pkl, 1.0f);
    dim3 gv(16, 64);
    prep_vt<<<gv, 256>>>(pv, pvth, pvtl);

    dim3 ga(L_SEQ / 128, 64);         // (8, 64)
    flash_mma<<<ga, 256, FSMEM>>>(pqh, pql, pkh, pkl, pvth, pvtl, mask, pctx);

    split_stack<<<4096, 256>>>(pctx, pc3);
    gemm_mma<<<gg, 256, GSMEM>>>(pc3, pwo3, bo, out);
}

// round 6
// speedup vs baseline: 2.4699x; 1.0218x over previous
#include <cuda_runtime.h>
#include <cuda_bf16.h>
#include <cstdint>

// ---------------------------------------------------------------------------
// MultiHeadAttention, fully tensor-core (mma.sync bf16x3, fp32 accum).
//  - 4 GEMMs: dedup'd stacked-K bf16x3 (AH/AL + WH/WL, loader remap).
//  - Q/K GEMM epilogues emit [bh][l][d] hi/lo bf16 (scale folded for Q).
//  - V GEMM epilogue transposes in-smem, emits [bh][d][l] hi/lo bf16.
//  - Flash epilogue emits split hi/lo context directly for the output GEMM.
// ---------------------------------------------------------------------------

#define L_SEQ 1024
#define NB    8
#define NH    8
#define DH    64
#define DM    512
#define M_TOK (L_SEQ * NB)
#define NCH   24            // 3 * 512 / 64 stacked-K chunks

// ---- scratch (device globals) ----
__device__ __nv_bfloat16 g_aqh[M_TOK * DM], g_aql[M_TOK * DM];
__device__ __nv_bfloat16 g_akh[M_TOK * DM], g_akl[M_TOK * DM];
__device__ __nv_bfloat16 g_avh[M_TOK * DM], g_avl[M_TOK * DM];
__device__ __nv_bfloat16 g_ch [M_TOK * DM], g_cl [M_TOK * DM];
__device__ __nv_bfloat16 g_wqh[DM * DM], g_wql[DM * DM];
__device__ __nv_bfloat16 g_wkh[DM * DM], g_wkl[DM * DM];
__device__ __nv_bfloat16 g_wvh[DM * DM], g_wvl[DM * DM];
__device__ __nv_bfloat16 g_woh[DM * DM], g_wol[DM * DM];
// attention operands: [bh][l][d] hi/lo, V transposed [bh][d][l]
__device__ __nv_bfloat16 g_qh[64 * L_SEQ * DH], g_ql[64 * L_SEQ * DH];
__device__ __nv_bfloat16 g_kh[64 * L_SEQ * DH], g_kl[64 * L_SEQ * DH];
__device__ __nv_bfloat16 g_vth[64 * DH * L_SEQ], g_vtl[64 * DH * L_SEQ];

// =============================== PTX helpers ===============================
__device__ __forceinline__ uint32_t smem_u32(const void* p) {
    uint32_t a;
    asm("{ .reg .u64 t; cvta.to.shared.u64 t, %1; cvt.u32.u64 %0, t; }"
        : "=r"(a) : "l"(p));
    return a;
}
__device__ __forceinline__ void cp16(uint32_t dst, const void* src) {
    asm volatile("cp.async.cg.shared.global [%0], [%1], 16;" :: "r"(dst), "l"(src));
}
__device__ __forceinline__ void cp_commit() {
    asm volatile("cp.async.commit_group;" ::: "memory");
}
template <int N> __device__ __forceinline__ void cp_wait() {
    asm volatile("cp.async.wait_group %0;" :: "n"(N) : "memory");
}
__device__ __forceinline__ void ldsm4(uint32_t& r0, uint32_t& r1,
                                      uint32_t& r2, uint32_t& r3, uint32_t addr) {
    asm volatile("ldmatrix.sync.aligned.m8n8.x4.shared.b16 {%0,%1,%2,%3}, [%4];"
                 : "=r"(r0), "=r"(r1), "=r"(r2), "=r"(r3) : "r"(addr));
}
__device__ __forceinline__ void mma16816(float* d, uint32_t a0, uint32_t a1,
                                         uint32_t a2, uint32_t a3,
                                         uint32_t b0, uint32_t b1) {
    asm volatile(
        "mma.sync.aligned.m16n8k16.row.col.f32.bf16.bf16.f32 "
        "{%0,%1,%2,%3}, {%4,%5,%6,%7}, {%8,%9}, {%0,%1,%2,%3};"
        : "+f"(d[0]), "+f"(d[1]), "+f"(d[2]), "+f"(d[3])
        : "r"(a0), "r"(a1), "r"(a2), "r"(a3), "r"(b0), "r"(b1));
}
__device__ __forceinline__ uint32_t swz(uint32_t off) {
    return off ^ ((off >> 3) & 0x70);
}
// pack two f32 -> bf16x2, 'hi' in upper half, 'lo' in lower half
__device__ __forceinline__ uint32_t cvt2bf(float hi, float lo) {
    uint32_t r;
    asm("cvt.rn.bf16x2.f32 %0, %1, %2;" : "=r"(r) : "f"(hi), "f"(lo));
    return r;
}
// residual word for a hi-word h against fp32 pair (v0 lower, v1 upper)
__device__ __forceinline__ uint32_t resid2bf(uint32_t h, float v0, float v1) {
    return cvt2bf(v1 - __uint_as_float(h & 0xffff0000u),
                  v0 - __uint_as_float(h << 16));
}

// =============== split kernels: fp32 -> bf16 hi/lo (dedup'd) ===============
__global__ __launch_bounds__(256) void split_in(const float* __restrict__ X,
                                                __nv_bfloat16* __restrict__ AH,
                                                __nv_bfloat16* __restrict__ AL) {
    int idx = blockIdx.x * 256 + threadIdx.x;
    int m = idx >> 7;
    int c = (idx & 127) * 4;
    float4 x = *(const float4*)&X[(size_t)m * DM + c];
    float xs[4] = {x.x, x.y, x.z, x.w};
    unsigned short hs[4], ls[4];
#pragma unroll
    for (int i = 0; i < 4; i++) {
        __nv_bfloat16 h = __float2bfloat16(xs[i]);
        __nv_bfloat16 l = __float2bfloat16(xs[i] - __bfloat162float(h));
        hs[i] = __bfloat16_as_ushort(h);
        ls[i] = __bfloat16_as_ushort(l);
    }
    size_t o = (size_t)m * DM + c;
    *(uint2*)&AH[o] = make_uint2((uint32_t)hs[0] | ((uint32_t)hs[1] << 16),
                                 (uint32_t)hs[2] | ((uint32_t)hs[3] << 16));
    *(uint2*)&AL[o] = make_uint2((uint32_t)ls[0] | ((uint32_t)ls[1] << 16),
                                 (uint32_t)ls[2] | ((uint32_t)ls[3] << 16));
}

__global__ __launch_bounds__(256) void split_w(const float* __restrict__ W,
                                               __nv_bfloat16* __restrict__ WH,
                                               __nv_bfloat16* __restrict__ WL) {
    int idx = blockIdx.x * 256 + threadIdx.x;
    int n = idx >> 9;
    int k = idx & 511;
    float x = W[(size_t)k * DM + n];
    __nv_bfloat16 h = __float2bfloat16(x);
    __nv_bfloat16 l = __float2bfloat16(x - __bfloat162float(h));
    WH[(size_t)n * DM + k] = h;
    WL[(size_t)n * DM + k] = l;
}

// ================== mma.sync bf16x3 GEMM with fused epilogues ==================
// Logical C[8192,512] = A @ W^T + bias, via 24 stacked-K chunks:
//   chunks 0-7: AH x WH, 8-15: AH x WL, 16-23: AL x WH.
// MODE 0: C fp32 + bias (final output)
// MODE 1: split to XH/XL in [bh][l][d] layout, scaled (Q/K projections)
// MODE 2: transpose in smem, split to XH/XL in [bh][d][l] layout (V projection)
#define GSMEM (1024 + 4 * 16384)

template <int MODE>
__global__ __launch_bounds__(256) void gemm_mma(
    const __nv_bfloat16* __restrict__ AH, const __nv_bfloat16* __restrict__ AL,
    const __nv_bfloat16* __restrict__ WH, const __nv_bfloat16* __restrict__ WL,
    const float* __restrict__ bias, float* __restrict__ C,
    __nv_bfloat16* __restrict__ XH, __nv_bfloat16* __restrict__ XL, float scale)
{
    extern __shared__ char smem_raw[];
    const uint32_t sbase = (smem_u32(smem_raw) + 1023) & ~1023u;
    const uint32_t SA[2] = {sbase,               sbase + 16384};
    const uint32_t SB[2] = {sbase + 2 * 16384,   sbase + 3 * 16384};

    const int tid  = threadIdx.x;
    const int lane = tid & 31;
    const int wid  = tid >> 5;
    const int wm   = wid >> 2;
    const int wn   = wid & 3;
    const int m0 = blockIdx.y * 128;
    const int n0 = blockIdx.x * 128;

    float acc[4][4][4];
#pragma unroll
    for (int i = 0; i < 4; i++)
#pragma unroll
        for (int j = 0; j < 4; j++)
#pragma unroll
            for (int e = 0; e < 4; e++) acc[i][j][e] = 0.0f;

    auto load_a = [&](uint32_t dst, int ch) {
        const __nv_bfloat16* src = (ch < 16) ? AH : AL;
        const int k0 = (ch & 7) * 64;
#pragma unroll
        for (int i = 0; i < 4; i++) {
            int idx = tid + i * 256;
            int r = idx >> 3, sg = idx & 7;
            cp16(dst + swz((uint32_t)(r * 128 + sg * 16)),
                 (const void*)(src + (size_t)(m0 + r) * DM + k0 + sg * 8));
        }
    };
    auto load_b = [&](uint32_t dst, int ch) {
        const __nv_bfloat16* src = (ch >= 8 && ch < 16) ? WL : WH;
        const int k0 = (ch & 7) * 64;
#pragma unroll
        for (int i = 0; i < 4; i++) {
            int idx = tid + i * 256;
            int r = idx >> 3, sg = idx & 7;
            cp16(dst + swz((uint32_t)(r * 128 + sg * 16)),
                 (const void*)(src + (size_t)(n0 + r) * DM + k0 + sg * 8));
        }
    };

    const int a_row = wm * 64 + (lane & 15);
    const int a_g16 = (lane >> 4) * 16;
    const int b_row = wn * 32 + (lane & 7) + ((lane >> 4) << 3);
    const int b_g16 = ((lane >> 3) & 1) * 16;

    load_a(SA[0], 0);
    load_b(SB[0], 0);
    cp_commit();

    for (int c = 0; c < NCH; c++) {
        if (c + 1 < NCH) {
            load_a(SA[(c + 1) & 1], c + 1);
            load_b(SB[(c + 1) & 1], c + 1);
            cp_commit();
            cp_wait<1>();
        } else {
            cp_wait<0>();
        }
        __syncthreads();

        const uint32_t sa = SA[c & 1];
        const uint32_t sb = SB[c & 1];
#pragma unroll
        for (int kk = 0; kk < 4; kk++) {
            uint32_t a[4][4];
#pragma unroll
            for (int i = 0; i < 4; i++) {
                uint32_t off = (uint32_t)((a_row + i * 16) * 128 + kk * 32 + a_g16);
                ldsm4(a[i][0], a[i][1], a[i][2], a[i][3], sa + swz(off));
            }
            uint32_t b[2][4];
#pragma unroll
            for (int jj = 0; jj < 2; jj++) {
                uint32_t off = (uint32_t)((b_row + jj * 16) * 128 + kk * 32 + b_g16);
                ldsm4(b[jj][0], b[jj][1], b[jj][2], b[jj][3], sb + swz(off));
            }
#pragma unroll
            for (int i = 0; i < 4; i++) {
#pragma unroll
                for (int j = 0; j < 4; j++) {
                    mma16816(acc[i][j], a[i][0], a[i][1], a[i][2], a[i][3],
                             b[j >> 1][(j & 1) * 2], b[j >> 1][(j & 1) * 2 + 1]);
                }
            }
        }
        __syncthreads();
    }

    if (MODE == 0) {
        // fp32 + bias
#pragma unroll
        for (int i = 0; i < 4; i++) {
#pragma unroll
            for (int j = 0; j < 4; j++) {
                int r  = m0 + wm * 64 + i * 16 + (lane >> 2);
                int cc = n0 + wn * 32 + j * 8 + (lane & 3) * 2;
                float b0 = bias[cc], b1 = bias[cc + 1];
                float2 v0 = make_float2(acc[i][j][0] + b0, acc[i][j][1] + b1);
                float2 v1 = make_float2(acc[i][j][2] + b0, acc[i][j][3] + b1);
                *(float2*)&C[(size_t)r * DM + cc]       = v0;
                *(float2*)&C[(size_t)(r + 8) * DM + cc] = v1;
            }
        }
    } else if (MODE == 1) {
        // split to [bh][l][d] hi/lo, scaled
#pragma unroll
        for (int i = 0; i < 4; i++) {
#pragma unroll
            for (int j = 0; j < 4; j++) {
                int r  = m0 + wm * 64 + i * 16 + (lane >> 2);
                int cc = n0 + wn * 32 + j * 8 + (lane & 3) * 2;
                float b0 = bias[cc], b1 = bias[cc + 1];
                float v0 = (acc[i][j][0] + b0) * scale;
                float v1 = (acc[i][j][1] + b1) * scale;
                float v2 = (acc[i][j][2] + b0) * scale;
                float v3 = (acc[i][j][3] + b1) * scale;
                int h = cc >> 6, d = cc & 63;
#pragma unroll
                for (int rr = 0; rr < 2; rr++) {
                    int row = r + rr * 8;
                    float a0 = rr ? v2 : v0, a1 = rr ? v3 : v1;
                    int l = row >> 3, bb = row & 7;
                    size_t off = (((size_t)(bb * 8 + h) * 1024) + l) * 64 + d;
                    uint32_t hw = cvt2bf(a1, a0);
                    *(uint32_t*)&XH[off] = hw;
                    *(uint32_t*)&XL[off] = resid2bf(hw, a0, a1);
                }
            }
        }
    } else {
        // MODE 2: stage fp32 tile in smem (xor-swizzled), transpose, split
        float* sm_f = (float*)(smem_raw + (sbase - smem_u32(smem_raw)));
#pragma unroll
        for (int i = 0; i < 4; i++) {
#pragma unroll
            for (int j = 0; j < 4; j++) {
                int rl = wm * 64 + i * 16 + (lane >> 2);
                int cl = wn * 32 + j * 8 + (lane & 3) * 2;
                float b0 = bias[n0 + cl], b1 = bias[n0 + cl + 1];
                sm_f[rl * 128 + (cl ^ (rl & 31))]             = acc[i][j][0] + b0;
                sm_f[rl * 128 + ((cl + 1) ^ (rl & 31))]       = acc[i][j][1] + b1;
                sm_f[(rl + 8) * 128 + (cl ^ ((rl + 8) & 31))]       = acc[i][j][2] + b0;
                sm_f[(rl + 8) * 128 + ((cl + 1) ^ ((rl + 8) & 31))] = acc[i][j][3] + b1;
            }
        }
        __syncthreads();
        const int h2 = tid >> 7;            // 0..1 (head within this n-block)
        const int d  = (tid >> 1) & 63;
        const int bp = (tid & 1) * 4;
        const int l0g = m0 >> 3;            // 16 l values per tile
        const int col = h2 * 64 + d;
        const int hglob = (n0 >> 6) + h2;
#pragma unroll
        for (int bi = 0; bi < 4; bi++) {
            int bb = bp + bi;
            int bh = bb * 8 + hglob;
            uint32_t wh[8], wl[8];
#pragma unroll
            for (int lp = 0; lp < 8; lp++) {
                int r0 = (2 * lp) * 8 + bb, r1 = (2 * lp + 1) * 8 + bb;
                float v0 = sm_f[r0 * 128 + (col ^ (r0 & 31))];
                float v1 = sm_f[r1 * 128 + (col ^ (r1 & 31))];
                wh[lp] = cvt2bf(v1, v0);
                wl[lp] = resid2bf(wh[lp], v0, v1);
            }
            size_t off = ((size_t)bh * 64 + d) * 1024 + l0g;
            *(uint4*)&XH[off]     = make_uint4(wh[0], wh[1], wh[2], wh[3]);
            *(uint4*)&XH[off + 8] = make_uint4(wh[4], wh[5], wh[6], wh[7]);
            *(uint4*)&XL[off]     = make_uint4(wl[0], wl[1], wl[2], wl[3]);
            *(uint4*)&XL[off + 8] = make_uint4(wl[4], wl[5], wl[6], wl[7]);
        }
    }
}

// ============ flash attention, mma.sync bf16x3 both GEMMs ============
#define FSMEM (1024 + 96 * 1024)

__global__ __launch_bounds__(256) void flash_mma(
    const __nv_bfloat16* __restrict__ qh, const __nv_bfloat16* __restrict__ ql,
    const __nv_bfloat16* __restrict__ kh, const __nv_bfloat16* __restrict__ kl,
    const __nv_bfloat16* __restrict__ vth, const __nv_bfloat16* __restrict__ vtl,
    const float* __restrict__ mask,
    __nv_bfloat16* __restrict__ CH, __nv_bfloat16* __restrict__ CL)
{
    extern __shared__ char smem_raw[];
    const uint32_t sbase = (smem_u32(smem_raw) + 1023) & ~1023u;
    const uint32_t QH = sbase, QL = sbase + 16384;
    const uint32_t BUF = sbase + 32768;

    const int tid = threadIdx.x, lane = tid & 31, wid = tid >> 5;
    const int bh = blockIdx.y;
    const int bb_ = bh >> 3, hh_ = bh & 7;
    const int l0 = blockIdx.x * 128;
    const size_t qoff = ((size_t)bh * 1024 + l0) * 64;
    const size_t koff = (size_t)bh * 1024 * 64;
    const size_t voff = (size_t)bh * 64 * 1024;

#pragma unroll
    for (int i = 0; i < 4; i++) {
        int idx = tid + i * 256;
        int r = idx >> 3, sg = idx & 7;
        uint32_t so = swz((uint32_t)(r * 128 + sg * 16));
        cp16(QH + so, (const void*)(qh + qoff + (size_t)r * 64 + sg * 8));
        cp16(QL + so, (const void*)(ql + qoff + (size_t)r * 64 + sg * 8));
    }
    cp_commit();

    auto load_kv = [&](int bb, int t) {
        const uint32_t base = BUF + bb * 32768;
#pragma unroll
        for (int i = 0; i < 2; i++) {
            int idx = tid + i * 256;
            int r = idx >> 3, sg = idx & 7;
            uint32_t so = swz((uint32_t)(r * 128 + sg * 16));
            cp16(base         + so, (const void*)(kh  + koff + (size_t)(t * 64 + r) * 64 + sg * 8));
            cp16(base + 8192  + so, (const void*)(kl  + koff + (size_t)(t * 64 + r) * 64 + sg * 8));
            cp16(base + 16384 + so, (const void*)(vth + voff + (size_t)r * 1024 + t * 64 + sg * 8));
            cp16(base + 24576 + so, (const void*)(vtl + voff + (size_t)r * 1024 + t * 64 + sg * 8));
        }
    };
    load_kv(0, 0);
    cp_commit();
    cp_wait<0>();
    __syncthreads();

    uint32_t Qh[4][4], Ql[4][4];
    {
        const int a_row = wid * 16 + (lane & 15);
        const uint32_t g16 = (uint32_t)((lane >> 4) * 16);
#pragma unroll
        for (int kk = 0; kk < 4; kk++) {
            uint32_t off = swz((uint32_t)(a_row * 128 + kk * 32) + g16);
            ldsm4(Qh[kk][0], Qh[kk][1], Qh[kk][2], Qh[kk][3], QH + off);
            ldsm4(Ql[kk][0], Ql[kk][1], Ql[kk][2], Ql[kk][3], QL + off);
        }
    }

    const int b_row = (lane & 7) + ((lane >> 4) << 3);
    const uint32_t b_g16 = (uint32_t)(((lane >> 3) & 1) * 16);

    float O[8][4];
#pragma unroll
    for (int j = 0; j < 8; j++)
#pragma unroll
        for (int e = 0; e < 4; e++) O[j][e] = 0.0f;
    float mrow0 = -1e30f, mrow1 = -1e30f, lrow0 = 0.0f, lrow1 = 0.0f;

    const int rq0 = l0 + wid * 16 + (lane >> 2);
    const int colq = (lane & 3) * 2;

    for (int t = 0; t < 16; t++) {
        if (t + 1 < 16) {
            load_kv((t + 1) & 1, t + 1);
            cp_commit();
            cp_wait<1>();
        } else {
            cp_wait<0>();
        }
        __syncthreads();
        const uint32_t base = BUF + (t & 1) * 32768;

        float S[8][4];
#pragma unroll
        for (int j = 0; j < 8; j++)
#pragma unroll
            for (int e = 0; e < 4; e++) S[j][e] = 0.0f;
#pragma unroll
        for (int kk = 0; kk < 4; kk++) {
            uint32_t bH[4][4], bL[4][4];
#pragma unroll
            for (int jj = 0; jj < 4; jj++) {
                uint32_t off = swz((uint32_t)((b_row + jj * 16) * 128 + kk * 32) + b_g16);
                ldsm4(bH[jj][0], bH[jj][1], bH[jj][2], bH[jj][3], base + off);
                ldsm4(bL[jj][0], bL[jj][1], bL[jj][2], bL[jj][3], base + 8192 + off);
            }
#pragma unroll
            for (int j = 0; j < 8; j++) {
                uint32_t h0 = bH[j >> 1][(j & 1) * 2], h1 = bH[j >> 1][(j & 1) * 2 + 1];
                uint32_t u0 = bL[j >> 1][(j & 1) * 2], u1 = bL[j >> 1][(j & 1) * 2 + 1];
                mma16816(S[j], Qh[kk][0], Qh[kk][1], Qh[kk][2], Qh[kk][3], h0, h1);
                mma16816(S[j], Qh[kk][0], Qh[kk][1], Qh[kk][2], Qh[kk][3], u0, u1);
                mma16816(S[j], Ql[kk][0], Ql[kk][1], Ql[kk][2], Ql[kk][3], h0, h1);
            }
        }

        const int kc = t * 64;
#pragma unroll
        for (int j = 0; j < 8; j++) {
            float2 m0 = *(const float2*)&mask[(size_t)rq0 * L_SEQ + kc + j * 8 + colq];
            float2 m1 = *(const float2*)&mask[(size_t)(rq0 + 8) * L_SEQ + kc + j * 8 + colq];
            S[j][0] += m0.x; S[j][1] += m0.y;
            S[j][2] += m1.x; S[j][3] += m1.y;
        }
        float mx0 = -1e30f, mx1 = -1e30f;
#pragma unroll
        for (int j = 0; j < 8; j++) {
            mx0 = fmaxf(mx0, fmaxf(S[j][0], S[j][1]));
            mx1 = fmaxf(mx1, fmaxf(S[j][2], S[j][3]));
        }
        mx0 = fmaxf(mx0, __shfl_xor_sync(0xffffffffu, mx0, 1));
        mx0 = fmaxf(mx0, __shfl_xor_sync(0xffffffffu, mx0, 2));
        mx1 = fmaxf(mx1, __shfl_xor_sync(0xffffffffu, mx1, 1));
        mx1 = fmaxf(mx1, __shfl_xor_sync(0xffffffffu, mx1, 2));
        float mn0 = fmaxf(mrow0, mx0), mn1 = fmaxf(mrow1, mx1);
        float al0 = __expf(mrow0 - mn0), al1 = __expf(mrow1 - mn1);
        mrow0 = mn0; mrow1 = mn1;
        float s0 = 0.0f, s1 = 0.0f;
#pragma unroll
        for (int j = 0; j < 8; j++) {
            S[j][0] = __expf(S[j][0] - mn0);
            S[j][1] = __expf(S[j][1] - mn0);
            S[j][2] = __expf(S[j][2] - mn1);
            S[j][3] = __expf(S[j][3] - mn1);
            s0 += S[j][0] + S[j][1];
            s1 += S[j][2] + S[j][3];
        }
        s0 += __shfl_xor_sync(0xffffffffu, s0, 1);
        s0 += __shfl_xor_sync(0xffffffffu, s0, 2);
        s1 += __shfl_xor_sync(0xffffffffu, s1, 1);
        s1 += __shfl_xor_sync(0xffffffffu, s1, 2);
        lrow0 = lrow0 * al0 + s0;
        lrow1 = lrow1 * al1 + s1;
#pragma unroll
        for (int j = 0; j < 8; j++) {
            O[j][0] *= al0; O[j][1] *= al0;
            O[j][2] *= al1; O[j][3] *= al1;
        }

        uint32_t Ph[4][4], Pl[4][4];
#pragma unroll
        for (int kk = 0; kk < 4; kk++) {
            const int j0 = 2 * kk, j1 = 2 * kk + 1;
            Ph[kk][0] = cvt2bf(S[j0][1], S[j0][0]);
            Ph[kk][1] = cvt2bf(S[j0][3], S[j0][2]);
            Ph[kk][2] = cvt2bf(S[j1][1], S[j1][0]);
            Ph[kk][3] = cvt2bf(S[j1][3], S[j1][2]);
#pragma unroll
            for (int e = 0; e < 4; e++) {
                const int jj = (e < 2) ? j0 : j1;
                const int lo = (e & 1) * 2;
                float plo = S[jj][lo]     - __uint_as_float(Ph[kk][e] << 16);
                float phi = S[jj][lo + 1] - __uint_as_float(Ph[kk][e] & 0xffff0000u);
                Pl[kk][e] = cvt2bf(phi, plo);
            }
        }

#pragma unroll
        for (int kk = 0; kk < 4; kk++) {
            uint32_t vH[4][4], vL[4][4];
#pragma unroll
            for (int jj = 0; jj < 4; jj++) {
                uint32_t off = swz((uint32_t)((b_row + jj * 16) * 128 + kk * 32) + b_g16);
                ldsm4(vH[jj][0], vH[jj][1], vH[jj][2], vH[jj][3], base + 16384 + off);
                ldsm4(vL[jj][0], vL[jj][1], vL[jj][2], vL[jj][3], base + 24576 + off);
            }
#pragma unroll
            for (int j = 0; j < 8; j++) {
                uint32_t h0 = vH[j >> 1][(j & 1) * 2], h1 = vH[j >> 1][(j & 1) * 2 + 1];
                uint32_t u0 = vL[j >> 1][(j & 1) * 2], u1 = vL[j >> 1][(j & 1) * 2 + 1];
                mma16816(O[j], Ph[kk][0], Ph[kk][1], Ph[kk][2], Ph[kk][3], h0, h1);
                mma16816(O[j], Ph[kk][0], Ph[kk][1], Ph[kk][2], Ph[kk][3], u0, u1);
                mma16816(O[j], Pl[kk][0], Pl[kk][1], Pl[kk][2], Pl[kk][3], h0, h1);
            }
        }
        __syncthreads();
    }

    // ---- normalize + split-write context (hi/lo) ----
    const float inv0 = 1.0f / lrow0, inv1 = 1.0f / lrow1;
    const size_t mtok0 = (size_t)rq0 * NB + bb_;
    const size_t mtok1 = (size_t)(rq0 + 8) * NB + bb_;
#pragma unroll
    for (int j = 0; j < 8; j++) {
        int cc = hh_ * 64 + j * 8 + colq;
        float v0 = O[j][0] * inv0, v1 = O[j][1] * inv0;
        float v2 = O[j][2] * inv1, v3 = O[j][3] * inv1;
        uint32_t h01 = cvt2bf(v1, v0);
        uint32_t h23 = cvt2bf(v3, v2);
        *(uint32_t*)&CH[mtok0 * DM + cc] = h01;
        *(uint32_t*)&CL[mtok0 * DM + cc] = resid2bf(h01, v0, v1);
        *(uint32_t*)&CH[mtok1 * DM + cc] = h23;
        *(uint32_t*)&CL[mtok1 * DM + cc] = resid2bf(h23, v2, v3);
    }
}

// ---------------- launch ----------------
extern "C" void kernel_launch(void* const* d_in, const int* in_sizes, int n_in,
                              void* d_out, int out_size) {
    (void)in_sizes; (void)n_in; (void)out_size;
    const float* Q    = (const float*)d_in[0];
    const float* K    = (const float*)d_in[1];
    const float* V    = (const float*)d_in[2];
    const float* mask = (const float*)d_in[3];
    const float* Wq   = (const float*)d_in[4];
    const float* bq   = (const float*)d_in[5];
    const float* Wk   = (const float*)d_in[6];
    const float* bk   = (const float*)d_in[7];
    const float* Wv   = (const float*)d_in[8];
    const float* bv   = (const float*)d_in[9];
    const float* Wo   = (const float*)d_in[10];
    const float* bo   = (const float*)d_in[11];
    float* out = (float*)d_out;

    __nv_bfloat16 *paqh, *paql, *pakh, *pakl, *pavh, *pavl, *pch, *pcl;
    __nv_bfloat16 *pwqh, *pwql, *pwkh, *pwkl, *pwvh, *pwvl, *pwoh, *pwol;
    __nv_bfloat16 *pqh, *pql, *pkh, *pkl, *pvth, *pvtl;
    cudaGetSymbolAddress((void**)&paqh, g_aqh);
    cudaGetSymbolAddress((void**)&paql, g_aql);
    cudaGetSymbolAddress((void**)&pakh, g_akh);
    cudaGetSymbolAddress((void**)&pakl, g_akl);
    cudaGetSymbolAddress((void**)&pavh, g_avh);
    cudaGetSymbolAddress((void**)&pavl, g_avl);
    cudaGetSymbolAddress((void**)&pch,  g_ch);
    cudaGetSymbolAddress((void**)&pcl,  g_cl);
    cudaGetSymbolAddress((void**)&pwqh, g_wqh);
    cudaGetSymbolAddress((void**)&pwql, g_wql);
    cudaGetSymbolAddress((void**)&pwkh, g_wkh);
    cudaGetSymbolAddress((void**)&pwkl, g_wkl);
    cudaGetSymbolAddress((void**)&pwvh, g_wvh);
    cudaGetSymbolAddress((void**)&pwvl, g_wvl);
    cudaGetSymbolAddress((void**)&pwoh, g_woh);
    cudaGetSymbolAddress((void**)&pwol, g_wol);
    cudaGetSymbolAddress((void**)&pqh,  g_qh);
    cudaGetSymbolAddress((void**)&pql,  g_ql);
    cudaGetSymbolAddress((void**)&pkh,  g_kh);
    cudaGetSymbolAddress((void**)&pkl,  g_kl);
    cudaGetSymbolAddress((void**)&pvth, g_vth);
    cudaGetSymbolAddress((void**)&pvtl, g_vtl);

    cudaFuncSetAttribute(gemm_mma<0>, cudaFuncAttributeMaxDynamicSharedMemorySize, GSMEM);
    cudaFuncSetAttribute(gemm_mma<1>, cudaFuncAttributeMaxDynamicSharedMemorySize, GSMEM);
    cudaFuncSetAttribute(gemm_mma<2>, cudaFuncAttributeMaxDynamicSharedMemorySize, GSMEM);
    cudaFuncSetAttribute(flash_mma, cudaFuncAttributeMaxDynamicSharedMemorySize, FSMEM);

    split_w<<<1024, 256>>>(Wq, pwqh, pwql);
    split_w<<<1024, 256>>>(Wk, pwkh, pwkl);
    split_w<<<1024, 256>>>(Wv, pwvh, pwvl);
    split_w<<<1024, 256>>>(Wo, pwoh, pwol);

    split_in<<<4096, 256>>>(Q, paqh, paql);
    split_in<<<4096, 256>>>(K, pakh, pakl);
    split_in<<<4096, 256>>>(V, pavh, pavl);

    dim3 gg(DM / 128, M_TOK / 128);   // (4, 64)
    gemm_mma<1><<<gg, 256, GSMEM>>>(paqh, paql, pwqh, pwql, bq, nullptr, pqh, pql, 0.125f);
    gemm_mma<1><<<gg, 256, GSMEM>>>(pakh, pakl, pwkh, pwkl, bk, nullptr, pkh, pkl, 1.0f);
    gemm_mma<2><<<gg, 256, GSMEM>>>(pavh, pavl, pwvh, pwvl, bv, nullptr, pvth, pvtl, 1.0f);

    dim3 ga(L_SEQ / 128, 64);         // (8, 64)
    flash_mma<<<ga, 256, FSMEM>>>(pqh, pql, pkh, pkl, pvth, pvtl, mask, pch, pcl);

    gemm_mma<0><<<gg, 256, GSMEM>>>(pch, pcl, pwoh, pwol, bo, out, nullptr, nullptr, 1.0f);
}